// round 3
// baseline (speedup 1.0000x reference)
#include <cuda_runtime.h>

// Problem constants
#define Bx 2048
#define Tt 512
#define Dd 6
#define Hh 40
#define Gg 160   // 4*H
#define GP 192   // padded gate stride (f32x2 m=2 overflow region)

#define NWARP 4          // warps per CTA
#define NB 4             // batch elements per warp
#define BPC (NWARP*NB)   // 16 batch per CTA
#define NCTA (Bx/BPC)    // 128 CTAs

// Shared memory layout (in floats)
#define OFF_WI0 0
#define OFF_WH0 (OFF_WI0 + Dd*Gg)        //   960
#define OFF_WI1 (OFF_WH0 + Hh*Gg)        //  7360
#define OFF_WH1 (OFF_WI1 + Hh*Gg)        // 13760
#define OFF_WI2 (OFF_WH1 + Hh*Gg)        // 20160
#define OFF_WH2 (OFF_WI2 + Hh*Gg)        // 26560
#define OFF_PAD (OFF_WH2 + Hh*Gg)        // 32960 (64-float tail pad for m2 overflow)
#define OFF_B0  (OFF_PAD + 64)           // 33024 (GP floats each, padded)
#define OFF_B1  (OFF_B0 + GP)
#define OFF_B2  (OFF_B1 + GP)
#define OFF_WOUT (OFF_B2 + GP)           // 33600
#define OFF_HD0 (OFF_WOUT + Hh)          // 33640  h duplicated pairs: BPC*H*2
#define OFF_HD1 (OFF_HD0 + BPC*Hh*2)
#define OFF_HD2 (OFF_HD1 + BPC*Hh*2)
#define OFF_C0  (OFF_HD2 + BPC*Hh*2)     // 37480  c scalar
#define OFF_C1  (OFF_C0 + BPC*Hh)
#define OFF_C2  (OFF_C1 + BPC*Hh)
#define OFF_GT  (OFF_C2 + BPC*Hh)        // 39400  gates: BPC * GP
#define OFF_XS  (OFF_GT + BPC*GP)        // 42472  x duplicated pairs: BPC*D*2
#define SMEM_FLOATS (OFF_XS + BPC*Dd*2)  // 42664 floats = 170656 B

typedef unsigned long long u64;

__device__ __forceinline__ u64 lds64(unsigned a) {
    u64 v; asm volatile("ld.shared.b64 %0, [%1];" : "=l"(v) : "r"(a)); return v;
}
__device__ __forceinline__ void sts64(unsigned a, u64 v) {
    asm volatile("st.shared.b64 [%0], %1;" :: "r"(a), "l"(v) : "memory");
}
__device__ __forceinline__ u64 ffma2(u64 a, u64 b, u64 c) {
    u64 d; asm("fma.rn.f32x2 %0, %1, %2, %3;" : "=l"(d) : "l"(a), "l"(b), "l"(c)); return d;
}

__device__ __forceinline__ float sigmoidf_(float x) {
    return __fdividef(1.0f, 1.0f + __expf(-x));
}
__device__ __forceinline__ float tanhf_(float x) {
    return __fdividef(2.0f, 1.0f + __expf(-2.0f * x)) - 1.0f;
}

// Gate accumulation, packed f32x2 over gate pairs.
// wl: byte addr of WT[0][2*lane]; row stride 640B; m offsets +256B.
// ha: byte addr of duplicated h (pairs (h,h)), element (b,k) at +(b*K+k)*8.
template<int K>
__device__ __forceinline__ void accum2(u64 acc[3][NB], unsigned wl, unsigned ha)
{
#pragma unroll 4
    for (int k = 0; k < K; k++) {
        u64 w0 = lds64(wl + k * 640);
        u64 w1 = lds64(wl + k * 640 + 256);
        u64 w2 = lds64(wl + k * 640 + 512);
#pragma unroll
        for (int b = 0; b < NB; b++) {
            u64 h = lds64(ha + (b * K + k) * 8);
            acc[0][b] = ffma2(w0, h, acc[0][b]);
            acc[1][b] = ffma2(w1, h, acc[1][b]);
            acc[2][b] = ffma2(w2, h, acc[2][b]);
        }
    }
}

__device__ __forceinline__ void init_bias2(u64 acc[3][NB], unsigned ba)
{
#pragma unroll
    for (int m = 0; m < 3; m++) {
        u64 bv = lds64(ba + m * 256);
#pragma unroll
        for (int b = 0; b < NB; b++) acc[m][b] = bv;
    }
}

__device__ __forceinline__ void store_gates2(const u64 acc[3][NB], unsigned ga)
{
#pragma unroll
    for (int m = 0; m < 3; m++)
#pragma unroll
        for (int b = 0; b < NB; b++)
            sts64(ga + b * (GP * 4) + m * 256, acc[m][b]);
}

// h/c update for the warp's NB*H units (gate order i,f,g,o).
// gsm: scalar float view (stride GP per batch); h written as duplicated pairs.
__device__ __forceinline__ void update_hc(const float* __restrict__ gsm,
                                          unsigned hda,
                                          float* __restrict__ csm, int lane)
{
#pragma unroll
    for (int r = 0; r < 5; r++) {            // NB*H / 32 = 160/32 = 5
        int idx = lane + 32 * r;             // 0..159
        int b = idx / Hh;
        int u = idx - b * Hh;
        float gi = gsm[b * GP + u];
        float gf = gsm[b * GP + 40 + u];
        float gg = gsm[b * GP + 80 + u];
        float go = gsm[b * GP + 120 + u];
        float iv = sigmoidf_(gi);
        float fv = sigmoidf_(gf);
        float gv = tanhf_(gg);
        float ov = sigmoidf_(go);
        float c = fmaf(fv, csm[b * Hh + u], iv * gv);
        csm[b * Hh + u] = c;
        float h = ov * tanhf_(c);
        asm volatile("st.shared.v2.f32 [%0], {%1, %2};"
                     :: "r"(hda + (unsigned)((b * Hh + u) * 8)), "f"(h), "f"(h) : "memory");
    }
}

extern __shared__ float sm[];

__global__ void __launch_bounds__(NWARP * 32, 1)
lstm_fused_kernel(const float* __restrict__ x,
                  const float* __restrict__ Wih0, const float* __restrict__ Whh0,
                  const float* __restrict__ bih0, const float* __restrict__ bhh0,
                  const float* __restrict__ Wih1, const float* __restrict__ Whh1,
                  const float* __restrict__ bih1, const float* __restrict__ bhh1,
                  const float* __restrict__ Wih2, const float* __restrict__ Whh2,
                  const float* __restrict__ bih2, const float* __restrict__ bhh2,
                  const float* __restrict__ Wout, const float* __restrict__ bout,
                  float* __restrict__ out)
{
    const int tid = threadIdx.x;

    // ---- Load weights into shared, transposed: WT[k*G + j] = W[j*K + k] ----
    {
        auto loadT = [&](const float* __restrict__ src, float* __restrict__ dst, int K) {
            for (int idx = tid; idx < Gg * K; idx += NWARP * 32) {
                int j = idx / K;
                int k = idx - j * K;
                dst[k * Gg + j] = src[idx];
            }
        };
        loadT(Wih0, sm + OFF_WI0, Dd);
        loadT(Whh0, sm + OFF_WH0, Hh);
        loadT(Wih1, sm + OFF_WI1, Hh);
        loadT(Whh1, sm + OFF_WH1, Hh);
        loadT(Wih2, sm + OFF_WI2, Hh);
        loadT(Whh2, sm + OFF_WH2, Hh);
        for (int idx = tid; idx < Gg; idx += NWARP * 32) {
            sm[OFF_B0 + idx] = bih0[idx] + bhh0[idx];
            sm[OFF_B1 + idx] = bih1[idx] + bhh1[idx];
            sm[OFF_B2 + idx] = bih2[idx] + bhh2[idx];
        }
        // zero pads (keeps garbage finite; never read into results anyway)
        for (int idx = tid; idx < 64; idx += NWARP * 32) {
            sm[OFF_PAD + idx] = 0.0f;
            sm[OFF_B0 + Gg + (idx & 31)] = 0.0f;
            sm[OFF_B1 + Gg + (idx & 31)] = 0.0f;
            sm[OFF_B2 + Gg + (idx & 31)] = 0.0f;
        }
        if (tid < Hh) sm[OFF_WOUT + tid] = Wout[tid];
        // zero h (duplicated) and c state: HD0..C2 contiguous
        for (int idx = tid; idx < 3 * BPC * Hh * 2 + 3 * BPC * Hh; idx += NWARP * 32)
            sm[OFF_HD0 + idx] = 0.0f;
    }
    __syncthreads();

    const int warp = tid >> 5;
    const int lane = tid & 31;
    const int bw = warp * NB;                         // batch offset inside CTA
    const int bglob = blockIdx.x * BPC + bw;          // global batch base for this warp

    const unsigned sbase = (unsigned)__cvta_generic_to_shared(sm);
    const unsigned laneB = lane * 8;                  // byte offset of this lane's j-pair

    const unsigned wi0 = sbase + OFF_WI0 * 4 + laneB;
    const unsigned wh0 = sbase + OFF_WH0 * 4 + laneB;
    const unsigned wi1 = sbase + OFF_WI1 * 4 + laneB;
    const unsigned wh1 = sbase + OFF_WH1 * 4 + laneB;
    const unsigned wi2 = sbase + OFF_WI2 * 4 + laneB;
    const unsigned wh2 = sbase + OFF_WH2 * 4 + laneB;
    const unsigned b0a = sbase + OFF_B0 * 4 + laneB;
    const unsigned b1a = sbase + OFF_B1 * 4 + laneB;
    const unsigned b2a = sbase + OFF_B2 * 4 + laneB;

    const unsigned hd0 = sbase + (OFF_HD0 + bw * Hh * 2) * 4;
    const unsigned hd1 = sbase + (OFF_HD1 + bw * Hh * 2) * 4;
    const unsigned hd2 = sbase + (OFF_HD2 + bw * Hh * 2) * 4;
    const unsigned xsa = sbase + (OFF_XS + bw * Dd * 2) * 4;
    const unsigned ga  = sbase + (OFF_GT + bw * GP) * 4 + laneB;

    float* gsm = sm + OFF_GT + bw * GP;
    float* c0  = sm + OFF_C0 + bw * Hh;
    float* c1  = sm + OFF_C1 + bw * Hh;
    float* c2  = sm + OFF_C2 + bw * Hh;
    const float* h2s = sm + OFF_HD2 + bw * Hh * 2;    // scalar view of duplicated h2

    const float boutv = bout[0];

    // x streaming: lanes 0..23 each own one (b,k) of the warp's [NB][D] slab.
    const int bb = lane / Dd;                 // 0..5 (only <NB used)
    const int kk = lane - bb * Dd;
    const int bbc = (bb < NB) ? bb : (NB - 1);  // clamp to stay in-bounds
    const float* xptr = x + ((size_t)(bglob + bbc) * Tt) * Dd + kk;
    float xr = xptr[0];                        // x at t=0

    const int ob = lane >> 3;                  // output reduction: b = lane/8
    const int sub = lane & 7;

    for (int t = 0; t < Tt; t++) {
        // stage x_t (duplicated pair) into shared, prefetch x_{t+1}
        if (lane < NB * Dd) {
            asm volatile("st.shared.v2.f32 [%0], {%1, %2};"
                         :: "r"(xsa + (unsigned)((bb * Dd + kk) * 8)), "f"(xr), "f"(xr) : "memory");
        }
        __syncwarp();
        {
            int tn = (t + 1 < Tt) ? (t + 1) : t;
            xr = xptr[tn * Dd];
        }

        u64 acc[3][NB];

        // ---- Layer 0: gates = Wih0@x_t + Whh0@h0 + bias ----
        init_bias2(acc, b0a);
        accum2<Dd>(acc, wi0, xsa);
        accum2<Hh>(acc, wh0, hd0);
        store_gates2(acc, ga);
        __syncwarp();
        update_hc(gsm, hd0, c0, lane);
        __syncwarp();

        // ---- Layer 1 ----
        init_bias2(acc, b1a);
        accum2<Hh>(acc, wi1, hd0);
        accum2<Hh>(acc, wh1, hd1);
        store_gates2(acc, ga);
        __syncwarp();
        update_hc(gsm, hd1, c1, lane);
        __syncwarp();

        // ---- Layer 2 ----
        init_bias2(acc, b2a);
        accum2<Hh>(acc, wi2, hd1);
        accum2<Hh>(acc, wh2, hd2);
        store_gates2(acc, ga);
        __syncwarp();
        update_hc(gsm, hd2, c2, lane);
        __syncwarp();

        // ---- Output projection: out[b,t] = dot(Wout, h2[b]) + bout ----
        float s = 0.0f;
#pragma unroll
        for (int q = 0; q < 5; q++) {
            int u = sub * 5 + q;
            s = fmaf(sm[OFF_WOUT + u], h2s[(ob * Hh + u) * 2], s);
        }
        s += __shfl_down_sync(0xffffffffu, s, 4, 8);
        s += __shfl_down_sync(0xffffffffu, s, 2, 8);
        s += __shfl_down_sync(0xffffffffu, s, 1, 8);
        if (sub == 0) out[(size_t)(bglob + ob) * Tt + t] = s + boutv;
        __syncwarp();
    }
}

extern "C" void kernel_launch(void* const* d_in, const int* in_sizes, int n_in,
                              void* d_out, int out_size)
{
    const float* x    = (const float*)d_in[0];
    const float* Wih0 = (const float*)d_in[1];
    const float* Whh0 = (const float*)d_in[2];
    const float* bih0 = (const float*)d_in[3];
    const float* bhh0 = (const float*)d_in[4];
    const float* Wih1 = (const float*)d_in[5];
    const float* Whh1 = (const float*)d_in[6];
    const float* bih1 = (const float*)d_in[7];
    const float* bhh1 = (const float*)d_in[8];
    const float* Wih2 = (const float*)d_in[9];
    const float* Whh2 = (const float*)d_in[10];
    const float* bih2 = (const float*)d_in[11];
    const float* bhh2 = (const float*)d_in[12];
    const float* Wout = (const float*)d_in[13];
    const float* bout = (const float*)d_in[14];
    float* out = (float*)d_out;

    (void)in_sizes; (void)n_in; (void)out_size;

    cudaFuncSetAttribute(lstm_fused_kernel,
                         cudaFuncAttributeMaxDynamicSharedMemorySize,
                         SMEM_FLOATS * (int)sizeof(float));

    lstm_fused_kernel<<<NCTA, NWARP * 32, SMEM_FLOATS * sizeof(float)>>>(
        x, Wih0, Whh0, bih0, bhh0, Wih1, Whh1, bih1, bhh1,
        Wih2, Whh2, bih2, bhh2, Wout, bout, out);
}

// round 4
// speedup vs baseline: 1.0009x; 1.0009x over previous
#include <cuda_runtime.h>

// Problem constants
#define Bx 2048
#define Tt 512
#define Dd 6
#define Hh 40
#define Gg 160   // 4*H
#define GP 192   // padded gate stride (f32x2 m=2 overflow region)

#define NWARP 4          // warps per CTA
#define NB 4             // batch elements per warp
#define BPC (NWARP*NB)   // 16 batch per CTA
#define NCTA (Bx/BPC)    // 128 CTAs

// Shared memory layout (in floats)
#define OFF_WI0 0
#define OFF_WH0 (OFF_WI0 + Dd*Gg)        //   960
#define OFF_WI1 (OFF_WH0 + Hh*Gg)        //  7360
#define OFF_WH1 (OFF_WI1 + Hh*Gg)        // 13760
#define OFF_WI2 (OFF_WH1 + Hh*Gg)        // 20160
#define OFF_WH2 (OFF_WI2 + Hh*Gg)        // 26560
#define OFF_PAD (OFF_WH2 + Hh*Gg)        // 32960 (64-float tail pad for m2 overflow)
#define OFF_B0  (OFF_PAD + 64)           // 33024 (GP floats each, padded)
#define OFF_B1  (OFF_B0 + GP)
#define OFF_B2  (OFF_B1 + GP)
#define OFF_WOUT (OFF_B2 + GP)           // 33600
#define OFF_HD0 (OFF_WOUT + Hh)          // 33640  h duplicated pairs: BPC*H*2
#define OFF_HD1 (OFF_HD0 + BPC*Hh*2)
#define OFF_HD2 (OFF_HD1 + BPC*Hh*2)
#define OFF_C0  (OFF_HD2 + BPC*Hh*2)     // 37480  c scalar
#define OFF_C1  (OFF_C0 + BPC*Hh)
#define OFF_C2  (OFF_C1 + BPC*Hh)
#define OFF_GT  (OFF_C2 + BPC*Hh)        // 39400  gates: BPC * GP
#define OFF_XS  (OFF_GT + BPC*GP)        // 42472  x duplicated pairs: BPC*D*2
#define SMEM_FLOATS (OFF_XS + BPC*Dd*2)  // 42664 floats = 170656 B

typedef unsigned long long u64;

__device__ __forceinline__ u64 lds64(unsigned a) {
    u64 v; asm volatile("ld.shared.b64 %0, [%1];" : "=l"(v) : "r"(a)); return v;
}
__device__ __forceinline__ void sts64(unsigned a, u64 v) {
    asm volatile("st.shared.b64 [%0], %1;" :: "r"(a), "l"(v) : "memory");
}
__device__ __forceinline__ u64 ffma2(u64 a, u64 b, u64 c) {
    u64 d; asm("fma.rn.f32x2 %0, %1, %2, %3;" : "=l"(d) : "l"(a), "l"(b), "l"(c)); return d;
}

__device__ __forceinline__ float sigmoidf_(float x) {
    return __fdividef(1.0f, 1.0f + __expf(-x));
}
__device__ __forceinline__ float tanhf_(float x) {
    return __fdividef(2.0f, 1.0f + __expf(-2.0f * x)) - 1.0f;
}

// Gate accumulation, packed f32x2 over gate pairs.
// wl: byte addr of WT[0][2*lane]; row stride 640B; m offsets +256B.
// ha: byte addr of duplicated h (pairs (h,h)), element (b,k) at +(b*K+k)*8.
template<int K>
__device__ __forceinline__ void accum2(u64 acc[3][NB], unsigned wl, unsigned ha)
{
#pragma unroll 4
    for (int k = 0; k < K; k++) {
        u64 w0 = lds64(wl + k * 640);
        u64 w1 = lds64(wl + k * 640 + 256);
        u64 w2 = lds64(wl + k * 640 + 512);
#pragma unroll
        for (int b = 0; b < NB; b++) {
            u64 h = lds64(ha + (b * K + k) * 8);
            acc[0][b] = ffma2(w0, h, acc[0][b]);
            acc[1][b] = ffma2(w1, h, acc[1][b]);
            acc[2][b] = ffma2(w2, h, acc[2][b]);
        }
    }
}

__device__ __forceinline__ void init_bias2(u64 acc[3][NB], unsigned ba)
{
#pragma unroll
    for (int m = 0; m < 3; m++) {
        u64 bv = lds64(ba + m * 256);
#pragma unroll
        for (int b = 0; b < NB; b++) acc[m][b] = bv;
    }
}

__device__ __forceinline__ void store_gates2(const u64 acc[3][NB], unsigned ga)
{
#pragma unroll
    for (int m = 0; m < 3; m++)
#pragma unroll
        for (int b = 0; b < NB; b++)
            sts64(ga + b * (GP * 4) + m * 256, acc[m][b]);
}

// h/c update for the warp's NB*H units (gate order i,f,g,o).
// gsm: scalar float view (stride GP per batch); h written as duplicated pairs.
__device__ __forceinline__ void update_hc(const float* __restrict__ gsm,
                                          unsigned hda,
                                          float* __restrict__ csm, int lane)
{
#pragma unroll
    for (int r = 0; r < 5; r++) {            // NB*H / 32 = 160/32 = 5
        int idx = lane + 32 * r;             // 0..159
        int b = idx / Hh;
        int u = idx - b * Hh;
        float gi = gsm[b * GP + u];
        float gf = gsm[b * GP + 40 + u];
        float gg = gsm[b * GP + 80 + u];
        float go = gsm[b * GP + 120 + u];
        float iv = sigmoidf_(gi);
        float fv = sigmoidf_(gf);
        float gv = tanhf_(gg);
        float ov = sigmoidf_(go);
        float c = fmaf(fv, csm[b * Hh + u], iv * gv);
        csm[b * Hh + u] = c;
        float h = ov * tanhf_(c);
        asm volatile("st.shared.v2.f32 [%0], {%1, %2};"
                     :: "r"(hda + (unsigned)((b * Hh + u) * 8)), "f"(h), "f"(h) : "memory");
    }
}

extern __shared__ float sm[];

__global__ void __launch_bounds__(NWARP * 32, 1)
lstm_fused_kernel(const float* __restrict__ x,
                  const float* __restrict__ Wih0, const float* __restrict__ Whh0,
                  const float* __restrict__ bih0, const float* __restrict__ bhh0,
                  const float* __restrict__ Wih1, const float* __restrict__ Whh1,
                  const float* __restrict__ bih1, const float* __restrict__ bhh1,
                  const float* __restrict__ Wih2, const float* __restrict__ Whh2,
                  const float* __restrict__ bih2, const float* __restrict__ bhh2,
                  const float* __restrict__ Wout, const float* __restrict__ bout,
                  float* __restrict__ out)
{
    const int tid = threadIdx.x;

    // ---- Load weights into shared, transposed: WT[k*G + j] = W[j*K + k] ----
    {
        auto loadT = [&](const float* __restrict__ src, float* __restrict__ dst, int K) {
            for (int idx = tid; idx < Gg * K; idx += NWARP * 32) {
                int j = idx / K;
                int k = idx - j * K;
                dst[k * Gg + j] = src[idx];
            }
        };
        loadT(Wih0, sm + OFF_WI0, Dd);
        loadT(Whh0, sm + OFF_WH0, Hh);
        loadT(Wih1, sm + OFF_WI1, Hh);
        loadT(Whh1, sm + OFF_WH1, Hh);
        loadT(Wih2, sm + OFF_WI2, Hh);
        loadT(Whh2, sm + OFF_WH2, Hh);
        for (int idx = tid; idx < Gg; idx += NWARP * 32) {
            sm[OFF_B0 + idx] = bih0[idx] + bhh0[idx];
            sm[OFF_B1 + idx] = bih1[idx] + bhh1[idx];
            sm[OFF_B2 + idx] = bih2[idx] + bhh2[idx];
        }
        // zero pads (keeps garbage finite; never read into results anyway)
        for (int idx = tid; idx < 64; idx += NWARP * 32) {
            sm[OFF_PAD + idx] = 0.0f;
            sm[OFF_B0 + Gg + (idx & 31)] = 0.0f;
            sm[OFF_B1 + Gg + (idx & 31)] = 0.0f;
            sm[OFF_B2 + Gg + (idx & 31)] = 0.0f;
        }
        if (tid < Hh) sm[OFF_WOUT + tid] = Wout[tid];
        // zero h (duplicated) and c state: HD0..C2 contiguous
        for (int idx = tid; idx < 3 * BPC * Hh * 2 + 3 * BPC * Hh; idx += NWARP * 32)
            sm[OFF_HD0 + idx] = 0.0f;
    }
    __syncthreads();

    const int warp = tid >> 5;
    const int lane = tid & 31;
    const int bw = warp * NB;                         // batch offset inside CTA
    const int bglob = blockIdx.x * BPC + bw;          // global batch base for this warp

    const unsigned sbase = (unsigned)__cvta_generic_to_shared(sm);
    const unsigned laneB = lane * 8;                  // byte offset of this lane's j-pair

    const unsigned wi0 = sbase + OFF_WI0 * 4 + laneB;
    const unsigned wh0 = sbase + OFF_WH0 * 4 + laneB;
    const unsigned wi1 = sbase + OFF_WI1 * 4 + laneB;
    const unsigned wh1 = sbase + OFF_WH1 * 4 + laneB;
    const unsigned wi2 = sbase + OFF_WI2 * 4 + laneB;
    const unsigned wh2 = sbase + OFF_WH2 * 4 + laneB;
    const unsigned b0a = sbase + OFF_B0 * 4 + laneB;
    const unsigned b1a = sbase + OFF_B1 * 4 + laneB;
    const unsigned b2a = sbase + OFF_B2 * 4 + laneB;

    const unsigned hd0 = sbase + (OFF_HD0 + bw * Hh * 2) * 4;
    const unsigned hd1 = sbase + (OFF_HD1 + bw * Hh * 2) * 4;
    const unsigned hd2 = sbase + (OFF_HD2 + bw * Hh * 2) * 4;
    const unsigned xsa = sbase + (OFF_XS + bw * Dd * 2) * 4;
    const unsigned ga  = sbase + (OFF_GT + bw * GP) * 4 + laneB;

    float* gsm = sm + OFF_GT + bw * GP;
    float* c0  = sm + OFF_C0 + bw * Hh;
    float* c1  = sm + OFF_C1 + bw * Hh;
    float* c2  = sm + OFF_C2 + bw * Hh;
    const float* h2s = sm + OFF_HD2 + bw * Hh * 2;    // scalar view of duplicated h2

    const float boutv = bout[0];

    // x streaming: lanes 0..23 each own one (b,k) of the warp's [NB][D] slab.
    const int bb = lane / Dd;                 // 0..5 (only <NB used)
    const int kk = lane - bb * Dd;
    const int bbc = (bb < NB) ? bb : (NB - 1);  // clamp to stay in-bounds
    const float* xptr = x + ((size_t)(bglob + bbc) * Tt) * Dd + kk;
    float xr = xptr[0];                        // x at t=0

    const int ob = lane >> 3;                  // output reduction: b = lane/8
    const int sub = lane & 7;

    for (int t = 0; t < Tt; t++) {
        // stage x_t (duplicated pair) into shared, prefetch x_{t+1}
        if (lane < NB * Dd) {
            asm volatile("st.shared.v2.f32 [%0], {%1, %2};"
                         :: "r"(xsa + (unsigned)((bb * Dd + kk) * 8)), "f"(xr), "f"(xr) : "memory");
        }
        __syncwarp();
        {
            int tn = (t + 1 < Tt) ? (t + 1) : t;
            xr = xptr[tn * Dd];
        }

        u64 acc[3][NB];

        // ---- Layer 0: gates = Wih0@x_t + Whh0@h0 + bias ----
        init_bias2(acc, b0a);
        accum2<Dd>(acc, wi0, xsa);
        accum2<Hh>(acc, wh0, hd0);
        store_gates2(acc, ga);
        __syncwarp();
        update_hc(gsm, hd0, c0, lane);
        __syncwarp();

        // ---- Layer 1 ----
        init_bias2(acc, b1a);
        accum2<Hh>(acc, wi1, hd0);
        accum2<Hh>(acc, wh1, hd1);
        store_gates2(acc, ga);
        __syncwarp();
        update_hc(gsm, hd1, c1, lane);
        __syncwarp();

        // ---- Layer 2 ----
        init_bias2(acc, b2a);
        accum2<Hh>(acc, wi2, hd1);
        accum2<Hh>(acc, wh2, hd2);
        store_gates2(acc, ga);
        __syncwarp();
        update_hc(gsm, hd2, c2, lane);
        __syncwarp();

        // ---- Output projection: out[b,t] = dot(Wout, h2[b]) + bout ----
        float s = 0.0f;
#pragma unroll
        for (int q = 0; q < 5; q++) {
            int u = sub * 5 + q;
            s = fmaf(sm[OFF_WOUT + u], h2s[(ob * Hh + u) * 2], s);
        }
        s += __shfl_down_sync(0xffffffffu, s, 4, 8);
        s += __shfl_down_sync(0xffffffffu, s, 2, 8);
        s += __shfl_down_sync(0xffffffffu, s, 1, 8);
        if (sub == 0) out[(size_t)(bglob + ob) * Tt + t] = s + boutv;
        __syncwarp();
    }
}

extern "C" void kernel_launch(void* const* d_in, const int* in_sizes, int n_in,
                              void* d_out, int out_size)
{
    const float* x    = (const float*)d_in[0];
    const float* Wih0 = (const float*)d_in[1];
    const float* Whh0 = (const float*)d_in[2];
    const float* bih0 = (const float*)d_in[3];
    const float* bhh0 = (const float*)d_in[4];
    const float* Wih1 = (const float*)d_in[5];
    const float* Whh1 = (const float*)d_in[6];
    const float* bih1 = (const float*)d_in[7];
    const float* bhh1 = (const float*)d_in[8];
    const float* Wih2 = (const float*)d_in[9];
    const float* Whh2 = (const float*)d_in[10];
    const float* bih2 = (const float*)d_in[11];
    const float* bhh2 = (const float*)d_in[12];
    const float* Wout = (const float*)d_in[13];
    const float* bout = (const float*)d_in[14];
    float* out = (float*)d_out;

    (void)in_sizes; (void)n_in; (void)out_size;

    cudaFuncSetAttribute(lstm_fused_kernel,
                         cudaFuncAttributeMaxDynamicSharedMemorySize,
                         SMEM_FLOATS * (int)sizeof(float));

    lstm_fused_kernel<<<NCTA, NWARP * 32, SMEM_FLOATS * sizeof(float)>>>(
        x, Wih0, Whh0, bih0, bhh0, Wih1, Whh1, bih1, bhh1,
        Wih2, Whh2, bih2, bhh2, Wout, bout, out);
}

// round 5
// speedup vs baseline: 1.2570x; 1.2559x over previous
#include <cuda_runtime.h>

#define Bx 2048
#define Tt 512
#define Dd 6
#define Hh 40
#define Gg 160
#define THREADS 320
#define BPC 14
#define NCTA 147   // 147*14 = 2058 >= 2048

// smem (float offsets). IN[b][128]: [0..6) x, [6..8) zero pad, [8..48) h0,
// [48..88) h1, [88..128) h2.  Batch stride 128 floats (512B, 16B-aligned).
#define INF 0
#define CF  (BPC*128)            // 1792: C[3][BPC][40]
#define PF  (CF + 3*BPC*Hh)      // 3472: PART[2][BPC][160]
#define WOF (PF + 2*BPC*Gg)      // 7952: Wout[40]
#define SMF (WOF + Hh)           // 7992 floats

typedef unsigned long long u64;
#define LOG2E 1.4426950408889634f

__device__ __forceinline__ u64 pk(float a, float b) {
    u64 r; asm("mov.b64 %0, {%1, %2};" : "=l"(r) : "f"(a), "f"(b)); return r;
}
__device__ __forceinline__ u64 ffma2(u64 a, u64 b, u64 c) {
    u64 d; asm("fma.rn.f32x2 %0, %1, %2, %3;" : "=l"(d) : "l"(a), "l"(b), "l"(c)); return d;
}
__device__ __forceinline__ u64 add2(u64 a, u64 b) {
    u64 d; asm("add.rn.f32x2 %0, %1, %2;" : "=l"(d) : "l"(a), "l"(b)); return d;
}
__device__ __forceinline__ float ex2f(float x) {
    float y; asm("ex2.approx.f32 %0, %1;" : "=f"(y) : "f"(x)); return y;
}
__device__ __forceinline__ float rcpf(float x) {
    float y; asm("rcp.approx.f32 %0, %1;" : "=f"(y) : "f"(x)); return y;
}
__device__ __forceinline__ float sigf(float x)  { return rcpf(1.0f + ex2f(-LOG2E * x)); }
__device__ __forceinline__ float tanhf_(float x){ return fmaf(2.0f, rcpf(1.0f + ex2f(-2.0f*LOG2E*x)), -1.0f); }

// Per-warp gate accumulation over this warp's k-half for all BPC batches.
// Weights in registers (u64 k-pairs); input read as 16B broadcasts.
// Writes s+bias straight to PART[half][b][g].
template<int NP>
__device__ __forceinline__ void accum_layer(const u64* wreg, const float* inbase,
                                            float* pst, float bias)
{
#pragma unroll
    for (int b = 0; b < BPC; b++) {
        const ulonglong2* hp = (const ulonglong2*)(inbase + b * 128);
        u64 a0 = 0ULL, a1 = 0ULL;
#pragma unroll
        for (int q = 0; q < NP / 2; q++) {
            ulonglong2 h = hp[q];
            a0 = ffma2(wreg[2*q],   h.x, a0);
            a1 = ffma2(wreg[2*q+1], h.y, a1);
        }
        a0 = add2(a0, a1);
        float u, v; asm("mov.b64 {%0, %1}, %2;" : "=f"(u), "=f"(v) : "l"(a0));
        pst[b * Gg] = u + v + bias;
    }
}

// Update one unit-pair: sum halves, activations, write c and h.
__device__ __forceinline__ void update2(const float* gp, float* cp, float* hp)
{
    float2 A, B;
    A = *(const float2*)(gp +   0); B = *(const float2*)(gp +   0 + BPC*Gg);
    float i0 = sigf(A.x + B.x),  i1 = sigf(A.y + B.y);
    A = *(const float2*)(gp +  40); B = *(const float2*)(gp +  40 + BPC*Gg);
    float f0 = sigf(A.x + B.x),  f1 = sigf(A.y + B.y);
    A = *(const float2*)(gp +  80); B = *(const float2*)(gp +  80 + BPC*Gg);
    float g0 = tanhf_(A.x + B.x), g1 = tanhf_(A.y + B.y);
    A = *(const float2*)(gp + 120); B = *(const float2*)(gp + 120 + BPC*Gg);
    float o0 = sigf(A.x + B.x),  o1 = sigf(A.y + B.y);
    float2 c = *(const float2*)cp;
    float cn0 = fmaf(f0, c.x, i0 * g0), cn1 = fmaf(f1, c.y, i1 * g1);
    *(float2*)cp = make_float2(cn0, cn1);
    *(float2*)hp = make_float2(o0 * tanhf_(cn0), o1 * tanhf_(cn1));
}

__global__ void __launch_bounds__(THREADS, 1)
lstm_fused_kernel(const float* __restrict__ x,
                  const float* __restrict__ Wih0, const float* __restrict__ Whh0,
                  const float* __restrict__ bih0, const float* __restrict__ bhh0,
                  const float* __restrict__ Wih1, const float* __restrict__ Whh1,
                  const float* __restrict__ bih1, const float* __restrict__ bhh1,
                  const float* __restrict__ Wih2, const float* __restrict__ Whh2,
                  const float* __restrict__ bih2, const float* __restrict__ bhh2,
                  const float* __restrict__ Wout, const float* __restrict__ bout,
                  float* __restrict__ out)
{
    __shared__ __align__(16) float smf[SMF];

    const int tid  = threadIdx.x;
    const int w    = tid >> 5;
    const int lane = tid & 31;
    const int half = w & 1;
    const int g    = (w >> 1) * 32 + lane;   // gate 0..159
    const int bglob = blockIdx.x * BPC;

    // zero IN + C; load Wout
    for (int i = tid; i < PF; i += THREADS) smf[i] = 0.0f;
    if (tid < Hh) smf[WOF + tid] = Wout[tid];

    // ---- weights into registers ----
    // Layer0 virtual k: [x(0..5), pad(6..7), h0(8..47)]; half covers 24 k.
    u64 wl0[12], wl1[20], wl2[20];
#pragma unroll
    for (int i = 0; i < 12; i++) {
        int k0 = half * 24 + 2 * i, k1 = k0 + 1;
        float a = (k0 < 6) ? Wih0[g*6 + k0] : ((k0 < 8) ? 0.0f : Whh0[g*40 + k0 - 8]);
        float b = (k1 < 6) ? Wih0[g*6 + k1] : ((k1 < 8) ? 0.0f : Whh0[g*40 + k1 - 8]);
        wl0[i] = pk(a, b);
    }
    {
        const float* s1 = (half ? Whh1 : Wih1) + g * 40;
        const float* s2 = (half ? Whh2 : Wih2) + g * 40;
#pragma unroll
        for (int i = 0; i < 20; i++) {
            wl1[i] = pk(s1[2*i], s1[2*i+1]);
            wl2[i] = pk(s2[2*i], s2[2*i+1]);
        }
    }
    const float bv0 = half ? (bih0[g] + bhh0[g]) : 0.0f;
    const float bv1 = half ? (bih1[g] + bhh1[g]) : 0.0f;
    const float bv2 = half ? (bih2[g] + bhh2[g]) : 0.0f;

    float* const pst = smf + PF + half * (BPC * Gg) + g;   // PART[half][.][g]

    // update-phase mapping: 280 threads, unit pairs
    const bool upd = tid < (BPC * Hh / 2);
    const int  ub  = tid / 20;
    const int  uu  = (tid % 20) * 2;
    const float* const gp = smf + PF + ub * Gg + uu;
    float* const cb = smf + CF + ub * Hh + uu;
    float* const hb = smf + INF + ub * 128 + uu;

    // x streaming: threads 0..83 own one (b,k)
    const int xb = tid / Dd, xk = tid - (tid / Dd) * Dd;
    int gb = bglob + xb; if (gb > Bx - 1) gb = Bx - 1;
    const float* const xptr = x + (size_t)gb * Tt * Dd + xk;
    float xr = (tid < BPC * Dd) ? xptr[0] : 0.0f;

    // output projection mapping (warps 0..3 → 16 slots, BPC=14 used)
    const int ob  = 4 * w + (lane >> 3);
    const int sub = lane & 7;
    const int obc = (ob < BPC) ? ob : 0;
    const float boutv = bout[0];

    __syncthreads();

    for (int t = 0; t < Tt; t++) {
        if (tid < BPC * Dd) smf[INF + xb * 128 + xk] = xr;
        __syncthreads();
        { int tn = (t + 1 < Tt) ? (t + 1) : t; xr = xptr[tn * Dd]; }

        // Layer 0: input = [x | pad | h0], half offset 24 floats
        accum_layer<12>(wl0, smf + INF + half * 24, pst, bv0);
        __syncthreads();
        if (upd) update2(gp, cb + 0 * BPC * Hh, hb + 8);
        __syncthreads();

        // Layer 1: half0 reads h0 (off 8), half1 reads h1 (off 48)
        accum_layer<20>(wl1, smf + INF + 8 + half * 40, pst, bv1);
        __syncthreads();
        if (upd) update2(gp, cb + 1 * BPC * Hh, hb + 48);
        __syncthreads();

        // Layer 2: half0 reads h1 (off 48), half1 reads h2 (off 88)
        accum_layer<20>(wl2, smf + INF + 48 + half * 40, pst, bv2);
        __syncthreads();
        if (upd) update2(gp, cb + 2 * BPC * Hh, hb + 88);
        __syncthreads();

        // output projection
        if (w < 4) {
            float s = 0.0f;
#pragma unroll
            for (int q = 0; q < 5; q++) {
                int u = sub * 5 + q;
                s = fmaf(smf[WOF + u], smf[INF + obc * 128 + 88 + u], s);
            }
            s += __shfl_down_sync(0xffffffffu, s, 4, 8);
            s += __shfl_down_sync(0xffffffffu, s, 2, 8);
            s += __shfl_down_sync(0xffffffffu, s, 1, 8);
            if (sub == 0 && ob < BPC && bglob + ob < Bx)
                out[(size_t)(bglob + ob) * Tt + t] = s + boutv;
        }
    }
}

extern "C" void kernel_launch(void* const* d_in, const int* in_sizes, int n_in,
                              void* d_out, int out_size)
{
    (void)in_sizes; (void)n_in; (void)out_size;
    lstm_fused_kernel<<<NCTA, THREADS>>>(
        (const float*)d_in[0],
        (const float*)d_in[1],  (const float*)d_in[2],
        (const float*)d_in[3],  (const float*)d_in[4],
        (const float*)d_in[5],  (const float*)d_in[6],
        (const float*)d_in[7],  (const float*)d_in[8],
        (const float*)d_in[9],  (const float*)d_in[10],
        (const float*)d_in[11], (const float*)d_in[12],
        (const float*)d_in[13], (const float*)d_in[14],
        (float*)d_out);
}

// round 6
// speedup vs baseline: 1.5060x; 1.1981x over previous
#include <cuda_runtime.h>

#define Bx 2048
#define Tt 512
#define Dd 6
#define Hh 40
#define Gg 160
#define BPC 14
#define NCTA 147          // 147*14 = 2058 >= 2048
#define THREADS 480       // 15 warps: 5 per layer

#define ISTR 128          // IN batch stride: [x6|pad2|h0 40|h1 40|h2 40]

// smem float offsets
#define INF 0
#define CF  (BPC*ISTR)             // 1792 : C[3][BPC][40]
#define GF  (CF + 3*BPC*Hh)        // 3472 : GATE[3][BPC][160]
#define WOF (GF + 3*BPC*Gg)        // 10192: Wout[40]
#define SMF (WOF + Hh + 8)         // 10240 floats = 40960 B

typedef unsigned long long u64;
#define LOG2E 1.4426950408889634f

__device__ __forceinline__ u64 pk(float a, float b) {
    u64 r; asm("mov.b64 %0, {%1, %2};" : "=l"(r) : "f"(a), "f"(b)); return r;
}
__device__ __forceinline__ u64 ffma2(u64 a, u64 b, u64 c) {
    u64 d; asm("fma.rn.f32x2 %0, %1, %2, %3;" : "=l"(d) : "l"(a), "l"(b), "l"(c)); return d;
}
__device__ __forceinline__ u64 add2(u64 a, u64 b) {
    u64 d; asm("add.rn.f32x2 %0, %1, %2;" : "=l"(d) : "l"(a), "l"(b)); return d;
}
__device__ __forceinline__ float ex2f(float x) {
    float y; asm("ex2.approx.f32 %0, %1;" : "=f"(y) : "f"(x)); return y;
}
__device__ __forceinline__ float rcpf(float x) {
    float y; asm("rcp.approx.f32 %0, %1;" : "=f"(y) : "f"(x)); return y;
}
__device__ __forceinline__ float sigf(float x)  { return rcpf(1.0f + ex2f(-LOG2E * x)); }
__device__ __forceinline__ float tanhf_(float x){ return fmaf(2.0f, rcpf(1.0f + ex2f(-2.0f*LOG2E*x)), -1.0f); }

// Gate accumulation for this lane's gate over all BPC batches.
// NQ = ulonglong2 (16B) loads per batch. Weights static in registers.
template<int NQ>
__device__ __forceinline__ void accum(const u64* __restrict__ wl,
                                      const float* __restrict__ inb,
                                      float* __restrict__ gout, float bias)
{
#pragma unroll
    for (int b = 0; b < BPC; b++) {
        const ulonglong2* hp = (const ulonglong2*)(inb + b * ISTR);
        u64 a0 = 0, a1 = 0, a2 = 0, a3 = 0;
#pragma unroll
        for (int q = 0; q < NQ; q += 2) {
            ulonglong2 v0 = hp[q];
            ulonglong2 v1 = hp[q + 1];
            a0 = ffma2(wl[2*q],     v0.x, a0);
            a1 = ffma2(wl[2*q + 1], v0.y, a1);
            a2 = ffma2(wl[2*q + 2], v1.x, a2);
            a3 = ffma2(wl[2*q + 3], v1.y, a3);
        }
        a0 = add2(a0, a2); a1 = add2(a1, a3); a0 = add2(a0, a1);
        float u, v; asm("mov.b64 {%0, %1}, %2;" : "=f"(u), "=f"(v) : "l"(a0));
        gout[b * Gg] = u + v + bias;
    }
}

__global__ void __launch_bounds__(THREADS, 1)
lstm_fused_kernel(const float* __restrict__ x,
                  const float* __restrict__ Wih0, const float* __restrict__ Whh0,
                  const float* __restrict__ bih0, const float* __restrict__ bhh0,
                  const float* __restrict__ Wih1, const float* __restrict__ Whh1,
                  const float* __restrict__ bih1, const float* __restrict__ bhh1,
                  const float* __restrict__ Wih2, const float* __restrict__ Whh2,
                  const float* __restrict__ bih2, const float* __restrict__ bhh2,
                  const float* __restrict__ Wout, const float* __restrict__ bout,
                  float* __restrict__ out)
{
    __shared__ __align__(16) float smf[SMF];

    const int tid  = threadIdx.x;
    const int w    = tid >> 5;
    const int lane = tid & 31;
    const int layer = (w < 5) ? 0 : ((w < 10) ? 1 : 2);
    const int g    = (w - layer * 5) * 32 + lane;   // gate 0..159
    const int bglob = blockIdx.x * BPC;

    // zero IN + C
    for (int i = tid; i < GF; i += THREADS) smf[i] = 0.0f;
    if (tid < Hh) smf[WOF + tid] = Wout[tid];

    // ---- weights into registers (full k for this lane's gate & layer) ----
    u64 wl[40];
    float bias;
    if (layer == 0) {
        // virtual k: [x 0..5 | pad 6..7 | h0 8..47] -> 24 pairs
#pragma unroll
        for (int i = 0; i < 24; i++) {
            int k0 = 2 * i, k1 = k0 + 1;
            float a = (k0 < 6) ? Wih0[g*6 + k0] : ((k0 < 8) ? 0.0f : Whh0[g*40 + k0 - 8]);
            float b = (k1 < 6) ? Wih0[g*6 + k1] : ((k1 < 8) ? 0.0f : Whh0[g*40 + k1 - 8]);
            wl[i] = pk(a, b);
        }
#pragma unroll
        for (int i = 24; i < 40; i++) wl[i] = 0ULL;
        bias = bih0[g] + bhh0[g];
    } else {
        const float* wi = (layer == 1 ? Wih1 : Wih2) + g * 40;
        const float* wh = (layer == 1 ? Whh1 : Whh2) + g * 40;
#pragma unroll
        for (int i = 0; i < 20; i++) {
            wl[i]      = pk(wi[2*i], wi[2*i + 1]);
            wl[20 + i] = pk(wh[2*i], wh[2*i + 1]);
        }
        bias = (layer == 1) ? (bih1[g] + bhh1[g]) : (bih2[g] + bhh2[g]);
    }
    const int base = (layer == 0) ? 0 : ((layer == 1) ? 8 : 48);
    const float* const inb  = smf + INF + base;
    float* const gout = smf + GF + layer * (BPC * Gg) + g;

    // ---- update-slot precompute (slot A = tid, slot B = tid + 480) ----
    // slot: l = sl/280, b = (sl%280)/20, unit pair up = (sl%20)*2
    const int slA = tid;
    const int lA = slA / 280, rA = slA - lA * 280, bA = rA / 20, uA = (rA - bA * 20) * 2;
    const bool hasB = tid < 360;
    const int slB = tid + 480;
    const int lB = slB / 280, rB = slB - lB * 280, bB = rB / 20, uB = (rB - bB * 20) * 2;
    const float* const gpA = smf + GF + lA * BPC * Gg + bA * Gg + uA;
    float* const cpA = smf + CF + lA * BPC * Hh + bA * Hh + uA;
    float* const hpA = smf + INF + bA * ISTR + 8 + 40 * lA + uA;
    const float* const gpB = smf + GF + lB * BPC * Gg + bB * Gg + uB;
    float* const cpB = smf + CF + lB * BPC * Hh + bB * Hh + uB;
    float* const hpB = smf + INF + bB * ISTR + 8 + 40 * lB + uB;

    // ---- x staging: threads 0..83 own (b,k) ----
    const int xb = tid / Dd, xk = tid - (tid / Dd) * Dd;
    int gbx = bglob + xb; if (gbx > Bx - 1) gbx = Bx - 1;
    const float* const xptr = x + (size_t)gbx * Tt * Dd + xk;
    float xr = 0.0f;
    if (tid < BPC * Dd) {
        smf[INF + xb * ISTR + xk] = xptr[0];   // x(0)
        xr = xptr[Dd];                          // x(1)
    }

    // ---- projection mapping (L0 warps, lanes grouped by 8) ----
    const int L  = w * 32 + lane;              // 0..159 for w<5
    const int pb = L >> 3;                     // 0..19
    const int sub = L & 7;
    const int pbc = (pb < BPC) ? pb : 0;
    int gbp = bglob + pb; if (gbp > Bx - 1) gbp = Bx - 1;
    const float boutv = bout[0];

    __syncthreads();

    for (int s = 0; s < Tt + 3; s++) {
        // ================= accum phase (all layers concurrent) =============
        const int tl = s - layer;
        if (tl >= 0 && tl < Tt) {
            if (layer == 0) accum<12>(wl, inb, gout, bias);
            else            accum<20>(wl, inb, gout, bias);
        }
        // projection of t=s-3 on L0 warps (h2 stable during accum)
        if (w < 5 && s >= 3) {
            float ssum = 0.0f;
#pragma unroll
            for (int j = 0; j < 5; j++) {
                int u = sub * 5 + j;
                ssum = fmaf(smf[WOF + u], smf[INF + pbc * ISTR + 88 + u], ssum);
            }
            ssum += __shfl_down_sync(0xffffffffu, ssum, 4, 8);
            ssum += __shfl_down_sync(0xffffffffu, ssum, 2, 8);
            ssum += __shfl_down_sync(0xffffffffu, ssum, 1, 8);
            if (sub == 0 && pb < BPC)
                out[(size_t)gbp * Tt + (s - 3)] = ssum + boutv;
        }
        __syncthreads();

        // ================= update phase (840 slots over 480 threads) ======
        {
            int ta = s - lA;
            if (ta >= 0 && ta < Tt) {
                float2 GI = *(const float2*)(gpA);
                float2 GG = *(const float2*)(gpA + 80);
                float2 GFo = *(const float2*)(gpA + 40);
                float2 GO = *(const float2*)(gpA + 120);
                float i0 = sigf(GI.x),  i1 = sigf(GI.y);
                float f0 = sigf(GFo.x), f1 = sigf(GFo.y);
                float g0 = tanhf_(GG.x), g1 = tanhf_(GG.y);
                float o0 = sigf(GO.x),  o1 = sigf(GO.y);
                float2 c = *(const float2*)cpA;
                float c0 = fmaf(f0, c.x, i0 * g0), c1 = fmaf(f1, c.y, i1 * g1);
                *(float2*)cpA = make_float2(c0, c1);
                *(float2*)hpA = make_float2(o0 * tanhf_(c0), o1 * tanhf_(c1));
            }
            if (hasB) {
                int tb = s - lB;
                if (tb >= 0 && tb < Tt) {
                    float2 GI = *(const float2*)(gpB);
                    float2 GG = *(const float2*)(gpB + 80);
                    float2 GFo = *(const float2*)(gpB + 40);
                    float2 GO = *(const float2*)(gpB + 120);
                    float i0 = sigf(GI.x),  i1 = sigf(GI.y);
                    float f0 = sigf(GFo.x), f1 = sigf(GFo.y);
                    float g0 = tanhf_(GG.x), g1 = tanhf_(GG.y);
                    float o0 = sigf(GO.x),  o1 = sigf(GO.y);
                    float2 c = *(const float2*)cpB;
                    float c0 = fmaf(f0, c.x, i0 * g0), c1 = fmaf(f1, c.y, i1 * g1);
                    *(float2*)cpB = make_float2(c0, c1);
                    *(float2*)hpB = make_float2(o0 * tanhf_(c0), o1 * tanhf_(c1));
                }
            }
        }
        // stage x(s+1) for next super-step, prefetch x(s+2)
        if (tid < BPC * Dd) {
            smf[INF + xb * ISTR + xk] = xr;
            int tn = s + 2; if (tn > Tt - 1) tn = Tt - 1;
            xr = xptr[tn * Dd];
        }
        __syncthreads();
    }
}

extern "C" void kernel_launch(void* const* d_in, const int* in_sizes, int n_in,
                              void* d_out, int out_size)
{
    (void)in_sizes; (void)n_in; (void)out_size;
    lstm_fused_kernel<<<NCTA, THREADS>>>(
        (const float*)d_in[0],
        (const float*)d_in[1],  (const float*)d_in[2],
        (const float*)d_in[3],  (const float*)d_in[4],
        (const float*)d_in[5],  (const float*)d_in[6],
        (const float*)d_in[7],  (const float*)d_in[8],
        (const float*)d_in[9],  (const float*)d_in[10],
        (const float*)d_in[11], (const float*)d_in[12],
        (const float*)d_in[13], (const float*)d_in[14],
        (float*)d_out);
}

// round 7
// speedup vs baseline: 1.5351x; 1.0193x over previous
#include <cuda_runtime.h>

#define Bx 2048
#define Tt 512
#define Dd 6
#define Hh 40
#define Gg 160
#define BPC 14
#define NCTA 147          // 147*14 = 2058 >= 2048
#define THREADS 480       // 15 warps: 5 per layer

#define ISTR 128          // IN batch stride: [x6|pad2|h0 40|h1 40|h2 40]

// smem float offsets
#define INF 0
#define CF  (BPC*ISTR)             // 1792 : C[3][BPC][40]
#define GF  (CF + 3*BPC*Hh)        // 3472 : GATE[3][BPC][160]
#define WOF (GF + 3*BPC*Gg)        // 10192: Wout[40]
#define SMF (WOF + Hh + 8)         // 10240 floats = 40960 B

typedef unsigned long long u64;
#define LOG2E 1.4426950408889634f

__device__ __forceinline__ u64 pk(float a, float b) {
    u64 r; asm("mov.b64 %0, {%1, %2};" : "=l"(r) : "f"(a), "f"(b)); return r;
}
__device__ __forceinline__ u64 ffma2(u64 a, u64 b, u64 c) {
    u64 d; asm("fma.rn.f32x2 %0, %1, %2, %3;" : "=l"(d) : "l"(a), "l"(b), "l"(c)); return d;
}
__device__ __forceinline__ u64 add2(u64 a, u64 b) {
    u64 d; asm("add.rn.f32x2 %0, %1, %2;" : "=l"(d) : "l"(a), "l"(b)); return d;
}
__device__ __forceinline__ float ex2f(float x) {
    float y; asm("ex2.approx.f32 %0, %1;" : "=f"(y) : "f"(x)); return y;
}
__device__ __forceinline__ float rcpf(float x) {
    float y; asm("rcp.approx.f32 %0, %1;" : "=f"(y) : "f"(x)); return y;
}
__device__ __forceinline__ float sigf(float x)  { return rcpf(1.0f + ex2f(-LOG2E * x)); }
__device__ __forceinline__ float tanhf_(float x){ return fmaf(2.0f, rcpf(1.0f + ex2f(-2.0f*LOG2E*x)), -1.0f); }

// 64-bit shared load: 1 wavefront for a broadcast (vs 2 for LDS.128).
// volatile so the compiler cannot re-vectorize pairs back into .128.
__device__ __forceinline__ u64 lds64(const float* p) {
    u64 v;
    asm volatile("ld.shared.b64 %0, [%1];" : "=l"(v) : "l"(__cvta_generic_to_shared(p)));
    return v;
}

// Gate accumulation for this lane's gate over all BPC batches.
// NP = u64 k-pair loads per batch. Weights static in registers.
template<int NP>
__device__ __forceinline__ void accum(const u64* __restrict__ wl,
                                      const float* __restrict__ inb,
                                      float* __restrict__ gout, float bias)
{
#pragma unroll
    for (int b = 0; b < BPC; b++) {
        const float* hp = inb + b * ISTR;
        u64 a0 = 0, a1 = 0;
#pragma unroll
        for (int q = 0; q < NP; q += 2) {
            u64 v0 = lds64(hp + 2 * q);
            u64 v1 = lds64(hp + 2 * q + 2);
            a0 = ffma2(wl[q],     v0, a0);
            a1 = ffma2(wl[q + 1], v1, a1);
        }
        a0 = add2(a0, a1);
        float u, v; asm("mov.b64 {%0, %1}, %2;" : "=f"(u), "=f"(v) : "l"(a0));
        gout[b * Gg] = u + v + bias;
    }
}

__global__ void __launch_bounds__(THREADS, 1)
lstm_fused_kernel(const float* __restrict__ x,
                  const float* __restrict__ Wih0, const float* __restrict__ Whh0,
                  const float* __restrict__ bih0, const float* __restrict__ bhh0,
                  const float* __restrict__ Wih1, const float* __restrict__ Whh1,
                  const float* __restrict__ bih1, const float* __restrict__ bhh1,
                  const float* __restrict__ Wih2, const float* __restrict__ Whh2,
                  const float* __restrict__ bih2, const float* __restrict__ bhh2,
                  const float* __restrict__ Wout, const float* __restrict__ bout,
                  float* __restrict__ out)
{
    __shared__ __align__(16) float smf[SMF];

    const int tid  = threadIdx.x;
    const int w    = tid >> 5;
    const int lane = tid & 31;
    const int layer = (w < 5) ? 0 : ((w < 10) ? 1 : 2);
    const int g    = (w - layer * 5) * 32 + lane;   // gate 0..159
    const int bglob = blockIdx.x * BPC;

    // zero IN + C
    for (int i = tid; i < GF; i += THREADS) smf[i] = 0.0f;
    if (tid < Hh) smf[WOF + tid] = Wout[tid];

    // ---- weights into registers (full k for this lane's gate & layer) ----
    u64 wl[40];
    float bias;
    if (layer == 0) {
        // virtual k: [x 0..5 | pad 6..7 | h0 8..47] -> 24 pairs
#pragma unroll
        for (int i = 0; i < 24; i++) {
            int k0 = 2 * i, k1 = k0 + 1;
            float a = (k0 < 6) ? Wih0[g*6 + k0] : ((k0 < 8) ? 0.0f : Whh0[g*40 + k0 - 8]);
            float b = (k1 < 6) ? Wih0[g*6 + k1] : ((k1 < 8) ? 0.0f : Whh0[g*40 + k1 - 8]);
            wl[i] = pk(a, b);
        }
#pragma unroll
        for (int i = 24; i < 40; i++) wl[i] = 0ULL;
        bias = bih0[g] + bhh0[g];
    } else {
        const float* wi = (layer == 1 ? Wih1 : Wih2) + g * 40;
        const float* wh = (layer == 1 ? Whh1 : Whh2) + g * 40;
#pragma unroll
        for (int i = 0; i < 20; i++) {
            wl[i]      = pk(wi[2*i], wi[2*i + 1]);
            wl[20 + i] = pk(wh[2*i], wh[2*i + 1]);
        }
        bias = (layer == 1) ? (bih1[g] + bhh1[g]) : (bih2[g] + bhh2[g]);
    }
    const int base = (layer == 0) ? 0 : ((layer == 1) ? 8 : 48);
    const float* const inb  = smf + INF + base;
    float* const gout = smf + GF + layer * (BPC * Gg) + g;

    // ---- update-slot precompute (slot A = tid, slot B = tid + 480) ----
    const int slA = tid;
    const int lA = slA / 280, rA = slA - lA * 280, bA = rA / 20, uA = (rA - bA * 20) * 2;
    const bool hasB = tid < 360;
    const int slB = tid + 480;
    const int lB = slB / 280, rB = slB - lB * 280, bB = rB / 20, uB = (rB - bB * 20) * 2;
    const float* const gpA = smf + GF + lA * BPC * Gg + bA * Gg + uA;
    float* const cpA = smf + CF + lA * BPC * Hh + bA * Hh + uA;
    float* const hpA = smf + INF + bA * ISTR + 8 + 40 * lA + uA;
    const float* const gpB = smf + GF + lB * BPC * Gg + bB * Gg + uB;
    float* const cpB = smf + CF + lB * BPC * Hh + bB * Hh + uB;
    float* const hpB = smf + INF + bB * ISTR + 8 + 40 * lB + uB;

    // ---- x staging: threads 0..83 own (b,k) ----
    const int xb = tid / Dd, xk = tid - (tid / Dd) * Dd;
    int gbx = bglob + xb; if (gbx > Bx - 1) gbx = Bx - 1;
    const float* const xptr = x + (size_t)gbx * Tt * Dd + xk;
    float xr = 0.0f;
    if (tid < BPC * Dd) {
        smf[INF + xb * ISTR + xk] = xptr[0];   // x(0)
        xr = xptr[Dd];                          // x(1)
    }

    // ---- projection mapping (L0 warps, lanes grouped by 8) ----
    const int L  = w * 32 + lane;              // 0..159 for w<5
    const int pb = L >> 3;                     // 0..19
    const int sub = L & 7;
    const int pbc = (pb < BPC) ? pb : 0;
    int gbp = bglob + pb; if (gbp > Bx - 1) gbp = Bx - 1;
    const float boutv = bout[0];

    __syncthreads();

    for (int s = 0; s < Tt + 3; s++) {
        // ================= accum phase (all layers concurrent) =============
        const int tl = s - layer;
        if (tl >= 0 && tl < Tt) {
            if (layer == 0) accum<24>(wl, inb, gout, bias);
            else            accum<40>(wl, inb, gout, bias);
        }
        // projection of t=s-3 on L0 warps (h2 stable during accum)
        if (w < 5 && s >= 3) {
            float ssum = 0.0f;
#pragma unroll
            for (int j = 0; j < 5; j++) {
                int u = sub * 5 + j;
                ssum = fmaf(smf[WOF + u], smf[INF + pbc * ISTR + 88 + u], ssum);
            }
            ssum += __shfl_down_sync(0xffffffffu, ssum, 4, 8);
            ssum += __shfl_down_sync(0xffffffffu, ssum, 2, 8);
            ssum += __shfl_down_sync(0xffffffffu, ssum, 1, 8);
            if (sub == 0 && pb < BPC)
                out[(size_t)gbp * Tt + (s - 3)] = ssum + boutv;
        }
        __syncthreads();

        // ================= update phase (840 slots over 480 threads) ======
        {
            int ta = s - lA;
            if (ta >= 0 && ta < Tt) {
                float2 GI = *(const float2*)(gpA);
                float2 GFo = *(const float2*)(gpA + 40);
                float2 GG = *(const float2*)(gpA + 80);
                float2 GO = *(const float2*)(gpA + 120);
                float i0 = sigf(GI.x),  i1 = sigf(GI.y);
                float f0 = sigf(GFo.x), f1 = sigf(GFo.y);
                float g0 = tanhf_(GG.x), g1 = tanhf_(GG.y);
                float o0 = sigf(GO.x),  o1 = sigf(GO.y);
                float2 c = *(const float2*)cpA;
                float c0 = fmaf(f0, c.x, i0 * g0), c1 = fmaf(f1, c.y, i1 * g1);
                *(float2*)cpA = make_float2(c0, c1);
                *(float2*)hpA = make_float2(o0 * tanhf_(c0), o1 * tanhf_(c1));
            }
            if (hasB) {
                int tb = s - lB;
                if (tb >= 0 && tb < Tt) {
                    float2 GI = *(const float2*)(gpB);
                    float2 GFo = *(const float2*)(gpB + 40);
                    float2 GG = *(const float2*)(gpB + 80);
                    float2 GO = *(const float2*)(gpB + 120);
                    float i0 = sigf(GI.x),  i1 = sigf(GI.y);
                    float f0 = sigf(GFo.x), f1 = sigf(GFo.y);
                    float g0 = tanhf_(GG.x), g1 = tanhf_(GG.y);
                    float o0 = sigf(GO.x),  o1 = sigf(GO.y);
                    float2 c = *(const float2*)cpB;
                    float c0 = fmaf(f0, c.x, i0 * g0), c1 = fmaf(f1, c.y, i1 * g1);
                    *(float2*)cpB = make_float2(c0, c1);
                    *(float2*)hpB = make_float2(o0 * tanhf_(c0), o1 * tanhf_(c1));
                }
            }
        }
        // stage x(s+1) for next super-step, prefetch x(s+2)
        if (tid < BPC * Dd) {
            smf[INF + xb * ISTR + xk] = xr;
            int tn = s + 2; if (tn > Tt - 1) tn = Tt - 1;
            xr = xptr[tn * Dd];
        }
        __syncthreads();
    }
}

extern "C" void kernel_launch(void* const* d_in, const int* in_sizes, int n_in,
                              void* d_out, int out_size)
{
    (void)in_sizes; (void)n_in; (void)out_size;
    lstm_fused_kernel<<<NCTA, THREADS>>>(
        (const float*)d_in[0],
        (const float*)d_in[1],  (const float*)d_in[2],
        (const float*)d_in[3],  (const float*)d_in[4],
        (const float*)d_in[5],  (const float*)d_in[6],
        (const float*)d_in[7],  (const float*)d_in[8],
        (const float*)d_in[9],  (const float*)d_in[10],
        (const float*)d_in[11], (const float*)d_in[12],
        (const float*)d_in[13], (const float*)d_in[14],
        (float*)d_out);
}

// round 8
// speedup vs baseline: 1.5610x; 1.0168x over previous
#include <cuda_runtime.h>

#define Bx 2048
#define Tt 512
#define Dd 6
#define Hh 40
#define Gg 160
#define BPC 14
#define NCTA 147          // 147*14 = 2058 >= 2048 (overflow batches clamp to 2047)
#define THREADS 256       // 8 warps; lane owns 2 adjacent gates

#define ISTR 130          // IN stride: [x6|pad2|h0 40|h1 40|h2 40|spare2]
#define GSTR 162          // GATE stride per batch (bank-spread)
#define LSTR (BPC*GSTR)   // GATE stride per layer

// smem float offsets
#define INF 0
#define CF  (BPC*ISTR)               // 1820 : C[3][BPC][40]
#define GF  (CF + 3*BPC*Hh)          // 3500 : GATE[3][BPC][GSTR]
#define WOF (GF + 3*LSTR)            // 10304: Wout[40]
#define SMF (WOF + Hh + 8)           // 10352 floats = 41408 B

typedef unsigned long long u64;
#define LOG2E 1.4426950408889634f

__device__ __forceinline__ u64 pk(float a, float b) {
    u64 r; asm("mov.b64 %0, {%1, %2};" : "=l"(r) : "f"(a), "f"(b)); return r;
}
__device__ __forceinline__ u64 ffma2(u64 a, u64 b, u64 c) {
    u64 d; asm("fma.rn.f32x2 %0, %1, %2, %3;" : "=l"(d) : "l"(a), "l"(b), "l"(c)); return d;
}
__device__ __forceinline__ u64 add2(u64 a, u64 b) {
    u64 d; asm("add.rn.f32x2 %0, %1, %2;" : "=l"(d) : "l"(a), "l"(b)); return d;
}
__device__ __forceinline__ float ex2f(float x) {
    float y; asm("ex2.approx.f32 %0, %1;" : "=f"(y) : "f"(x)); return y;
}
__device__ __forceinline__ float rcpf(float x) {
    float y; asm("rcp.approx.f32 %0, %1;" : "=f"(y) : "f"(x)); return y;
}
__device__ __forceinline__ float sigf(float x)  { return rcpf(1.0f + ex2f(-LOG2E * x)); }
__device__ __forceinline__ float tanhf_(float x){ return fmaf(2.0f, rcpf(1.0f + ex2f(-2.0f*LOG2E*x)), -1.0f); }

__device__ __forceinline__ u64 lds64(const float* p) {
    u64 v;
    asm volatile("ld.shared.b64 %0, [%1];" : "=l"(v) : "l"(__cvta_generic_to_shared(p)));
    return v;
}
__device__ __forceinline__ void sts64v(float* p, float a, float b) {
    asm volatile("st.shared.v2.f32 [%0], {%1, %2};"
                 :: "l"(__cvta_generic_to_shared(p)), "f"(a), "f"(b) : "memory");
}

// Accumulate 2 gates (A,B) over NP k-pairs for all BPC batches.
// One broadcast LDS.64 per k-pair feeds 2 FFMA2 (both gates).
template<int NP>
__device__ __forceinline__ void accum2g(const u64* __restrict__ wa,
                                        const u64* __restrict__ wb,
                                        const float* __restrict__ inb,
                                        float* __restrict__ gout,
                                        float biasA, float biasB)
{
#pragma unroll 2
    for (int b = 0; b < BPC; b++) {
        const float* hp = inb + b * ISTR;
        u64 a0 = 0, a1 = 0, c0 = 0, c1 = 0;
#pragma unroll
        for (int q = 0; q < NP; q += 2) {
            u64 v0 = lds64(hp + 2 * q);
            u64 v1 = lds64(hp + 2 * q + 2);
            a0 = ffma2(wa[q],     v0, a0);
            c0 = ffma2(wb[q],     v0, c0);
            a1 = ffma2(wa[q + 1], v1, a1);
            c1 = ffma2(wb[q + 1], v1, c1);
        }
        a0 = add2(a0, a1); c0 = add2(c0, c1);
        float ua, va, ub, vb;
        asm("mov.b64 {%0, %1}, %2;" : "=f"(ua), "=f"(va) : "l"(a0));
        asm("mov.b64 {%0, %1}, %2;" : "=f"(ub), "=f"(vb) : "l"(c0));
        sts64v(gout + b * GSTR, ua + va + biasA, ub + vb + biasB);
    }
}

__global__ void __launch_bounds__(THREADS, 1)
lstm_fused_kernel(const float* __restrict__ x,
                  const float* __restrict__ Wih0, const float* __restrict__ Whh0,
                  const float* __restrict__ bih0, const float* __restrict__ bhh0,
                  const float* __restrict__ Wih1, const float* __restrict__ Whh1,
                  const float* __restrict__ bih1, const float* __restrict__ bhh1,
                  const float* __restrict__ Wih2, const float* __restrict__ Whh2,
                  const float* __restrict__ bih2, const float* __restrict__ bhh2,
                  const float* __restrict__ Wout, const float* __restrict__ bout,
                  float* __restrict__ out)
{
    __shared__ __align__(16) float smf[SMF];

    const int tid  = threadIdx.x;
    const int w    = tid >> 5;
    const int bglob = blockIdx.x * BPC;

    // zero IN + C
    for (int i = tid; i < GF; i += THREADS) smf[i] = 0.0f;
    if (tid < Hh) smf[WOF + tid] = Wout[tid];

    // ---- gate-slot mapping: slot sl owns gates (2sl, 2sl+1) of layer sl/80 ----
    const int sl    = (tid < 240) ? tid : 239;    // clamp: spare lanes duplicate last pair
    const int layer = sl / 80;
    const int lg    = 2 * (sl - layer * 80);      // even gate index 0..158

    // ---- weights into registers ----
    u64 wa[40], wb[40];
    float biasA, biasB;
    {
        const int gA = lg, gB = lg + 1;
        if (layer == 0) {
            // virtual k-pairs: [x(3) | pad(1) | h0(20) | zero(16)]
#pragma unroll
            for (int i = 0; i < 3; i++) {
                wa[i] = pk(Wih0[gA*6 + 2*i], Wih0[gA*6 + 2*i + 1]);
                wb[i] = pk(Wih0[gB*6 + 2*i], Wih0[gB*6 + 2*i + 1]);
            }
            wa[3] = 0ULL; wb[3] = 0ULL;
#pragma unroll
            for (int i = 0; i < 20; i++) {
                wa[4 + i] = pk(Whh0[gA*40 + 2*i], Whh0[gA*40 + 2*i + 1]);
                wb[4 + i] = pk(Whh0[gB*40 + 2*i], Whh0[gB*40 + 2*i + 1]);
            }
#pragma unroll
            for (int i = 24; i < 40; i++) { wa[i] = 0ULL; wb[i] = 0ULL; }
            biasA = bih0[gA] + bhh0[gA];
            biasB = bih0[gB] + bhh0[gB];
        } else {
            const float* wi = (layer == 1 ? Wih1 : Wih2);
            const float* wh = (layer == 1 ? Whh1 : Whh2);
#pragma unroll
            for (int i = 0; i < 20; i++) {
                wa[i]      = pk(wi[gA*40 + 2*i], wi[gA*40 + 2*i + 1]);
                wb[i]      = pk(wi[gB*40 + 2*i], wi[gB*40 + 2*i + 1]);
                wa[20 + i] = pk(wh[gA*40 + 2*i], wh[gA*40 + 2*i + 1]);
                wb[20 + i] = pk(wh[gB*40 + 2*i], wh[gB*40 + 2*i + 1]);
            }
            biasA = (layer == 1) ? (bih1[gA] + bhh1[gA]) : (bih2[gA] + bhh2[gA]);
            biasB = (layer == 1) ? (bih1[gB] + bhh1[gB]) : (bih2[gB] + bhh2[gB]);
        }
    }
    const int base = (layer == 0) ? 0 : ((layer == 1) ? 8 : 48);
    const float* const inb = smf + INF + base;
    float* const gout = smf + GF + layer * LSTR + lg;

    // ---- update-slot precompute: slots tid+256j, j=0..3 (840 total) ----
    int uoffG[4], uoffC[4], uoffH[4], ulay[4]; bool uact[4];
#pragma unroll
    for (int j = 0; j < 4; j++) {
        int si = tid + 256 * j;
        uact[j] = si < 840;
        int sc = uact[j] ? si : 0;
        int l = sc / 280, r = sc - l * 280, b = r / 20, u = (r - b * 20) * 2;
        ulay[j]  = l;
        uoffG[j] = GF + l * LSTR + b * GSTR + u;
        uoffC[j] = CF + (l * BPC + b) * Hh + u;
        uoffH[j] = INF + b * ISTR + 8 + 40 * l + u;
    }

    // ---- x staging: threads 0..83 own (b,k) ----
    const int xb = tid / Dd, xk = tid - (tid / Dd) * Dd;
    int gbx = bglob + xb; if (gbx > Bx - 1) gbx = Bx - 1;
    const float* const xptr = x + (size_t)gbx * Tt * Dd + xk;
    float xr = 0.0f;
    if (tid < BPC * Dd) {
        smf[INF + xb * ISTR + xk] = xptr[0];   // x(0)
        xr = xptr[Dd];                          // x(1)
    }

    // ---- projection mapping: warps 0,1 (64 lanes), 4 lanes per batch ----
    const int pb  = tid >> 2;                  // 0..15 (for tid<64)
    const int sub = tid & 3;
    const int pbc = (pb < BPC) ? pb : 0;
    int gbp = bglob + pb; if (gbp > Bx - 1) gbp = Bx - 1;
    const float boutv = bout[0];

    __syncthreads();

    for (int s = 0; s < Tt + 3; s++) {
        // ============== accum phase (all layers concurrent) ==============
        if (w < 2) accum2g<24>(wa, wb, inb, gout, biasA, biasB);
        else       accum2g<40>(wa, wb, inb, gout, biasA, biasB);

        // projection of t=s-3 on warps 0,1 (h2(s-3) stable during accum)
        if (w < 2 && s >= 3) {
            float ssum = 0.0f;
#pragma unroll
            for (int j = 0; j < 10; j++) {
                int u = sub * 10 + j;
                ssum = fmaf(smf[WOF + u], smf[INF + pbc * ISTR + 88 + u], ssum);
            }
            ssum += __shfl_down_sync(0xffffffffu, ssum, 2, 4);
            ssum += __shfl_down_sync(0xffffffffu, ssum, 1, 4);
            if (sub == 0 && pb < BPC)
                out[(size_t)gbp * Tt + (s - 3)] = ssum + boutv;
        }
        __syncthreads();

        // ============== update phase (840 slots over 256 threads) ========
#pragma unroll
        for (int j = 0; j < 4; j++) {
            int ta = s - ulay[j];
            if (uact[j] && ta >= 0 && ta < Tt) {
                const float* gp = smf + uoffG[j];
                float* cp = smf + uoffC[j];
                float* hp = smf + uoffH[j];
                float2 GI = *(const float2*)(gp);
                float2 GFo = *(const float2*)(gp + 40);
                float2 GG = *(const float2*)(gp + 80);
                float2 GO = *(const float2*)(gp + 120);
                float i0 = sigf(GI.x),  i1 = sigf(GI.y);
                float f0 = sigf(GFo.x), f1 = sigf(GFo.y);
                float g0 = tanhf_(GG.x), g1 = tanhf_(GG.y);
                float o0 = sigf(GO.x),  o1 = sigf(GO.y);
                float2 c = *(const float2*)cp;
                float c0 = fmaf(f0, c.x, i0 * g0), c1 = fmaf(f1, c.y, i1 * g1);
                *(float2*)cp = make_float2(c0, c1);
                *(float2*)hp = make_float2(o0 * tanhf_(c0), o1 * tanhf_(c1));
            }
        }
        // stage x(s+1), prefetch x(s+2)
        if (tid < BPC * Dd) {
            smf[INF + xb * ISTR + xk] = xr;
            int tn = s + 2; if (tn > Tt - 1) tn = Tt - 1;
            xr = xptr[tn * Dd];
        }
        __syncthreads();
    }
}

extern "C" void kernel_launch(void* const* d_in, const int* in_sizes, int n_in,
                              void* d_out, int out_size)
{
    (void)in_sizes; (void)n_in; (void)out_size;
    lstm_fused_kernel<<<NCTA, THREADS>>>(
        (const float*)d_in[0],
        (const float*)d_in[1],  (const float*)d_in[2],
        (const float*)d_in[3],  (const float*)d_in[4],
        (const float*)d_in[5],  (const float*)d_in[6],
        (const float*)d_in[7],  (const float*)d_in[8],
        (const float*)d_in[9],  (const float*)d_in[10],
        (const float*)d_in[11], (const float*)d_in[12],
        (const float*)d_in[13], (const float*)d_in[14],
        (float*)d_out);
}

// round 10
// speedup vs baseline: 1.6473x; 1.0553x over previous
#include <cuda_runtime.h>

#define Bx 2048
#define Tt 512
#define Dd 6
#define Hh 40
#define Gg 160
#define BPC 14
#define NCTA 147          // 147*14 = 2058 >= 2048
#define THREADS 480       // 480 slots: (3 layers x 80 gate-pairs x 2 k-halves)

#define ISTR 132          // IN stride (16B-multiple): [x6|pad2|h0 40|h1 40|h2 40|spare4]
#define GSTR 162          // PART stride per batch
#define PHALF (3*BPC*GSTR)

// smem float offsets
#define INF 0
#define CF  (BPC*ISTR)               // 1848 : C[3][BPC][40]
#define PF  (CF + 3*BPC*Hh)          // 3528 : PART[2][3][BPC][GSTR]
#define WOF (PF + 2*PHALF)           // 17136: Wout[40]
#define SMF (WOF + Hh + 8)           // 17184 floats = 68736 B (dynamic)

typedef unsigned long long u64;
#define LOG2E 1.4426950408889634f

__device__ __forceinline__ u64 pk(float a, float b) {
    u64 r; asm("mov.b64 %0, {%1, %2};" : "=l"(r) : "f"(a), "f"(b)); return r;
}
__device__ __forceinline__ u64 ffma2(u64 a, u64 b, u64 c) {
    u64 d; asm("fma.rn.f32x2 %0, %1, %2, %3;" : "=l"(d) : "l"(a), "l"(b), "l"(c)); return d;
}
__device__ __forceinline__ u64 add2(u64 a, u64 b) {
    u64 d; asm("add.rn.f32x2 %0, %1, %2;" : "=l"(d) : "l"(a), "l"(b)); return d;
}
__device__ __forceinline__ float ex2f(float x) {
    float y; asm("ex2.approx.f32 %0, %1;" : "=f"(y) : "f"(x)); return y;
}
__device__ __forceinline__ float rcpf(float x) {
    float y; asm("rcp.approx.f32 %0, %1;" : "=f"(y) : "f"(x)); return y;
}
__device__ __forceinline__ float sigf(float x)  { return rcpf(1.0f + ex2f(-LOG2E * x)); }
__device__ __forceinline__ float tanhf_(float x){ return fmaf(2.0f, rcpf(1.0f + ex2f(-2.0f*LOG2E*x)), -1.0f); }

__device__ __forceinline__ void sts64v(float* p, float a, float b) {
    asm volatile("st.shared.v2.f32 [%0], {%1, %2};"
                 :: "l"(__cvta_generic_to_shared(p)), "f"(a), "f"(b) : "memory");
}

// Accumulate 2 gates (A,B) over NU u64 k-pairs (one k-half) for all batches.
// inb 16B-aligned; loads are warp-uniform broadcasts (ulonglong2).
template<int NU>
__device__ __forceinline__ void accum2g(const u64* __restrict__ wa,
                                        const u64* __restrict__ wb,
                                        const float* __restrict__ inb,
                                        float* __restrict__ pout,
                                        float biasA, float biasB)
{
#pragma unroll 2
    for (int b = 0; b < BPC; b++) {
        const ulonglong2* hp = (const ulonglong2*)(inb + b * ISTR);
        u64 a0 = 0, a1 = 0, c0 = 0, c1 = 0;
#pragma unroll
        for (int q = 0; q < NU / 2; q++) {
            ulonglong2 v = hp[q];
            a0 = ffma2(wa[2*q],     v.x, a0);
            c0 = ffma2(wb[2*q],     v.x, c0);
            a1 = ffma2(wa[2*q + 1], v.y, a1);
            c1 = ffma2(wb[2*q + 1], v.y, c1);
        }
        a0 = add2(a0, a1); c0 = add2(c0, c1);
        float ua, va, ub, vb;
        asm("mov.b64 {%0, %1}, %2;" : "=f"(ua), "=f"(va) : "l"(a0));
        asm("mov.b64 {%0, %1}, %2;" : "=f"(ub), "=f"(vb) : "l"(c0));
        sts64v(pout + b * GSTR, ua + va + biasA, ub + vb + biasB);
    }
}

extern __shared__ float smf[];

__global__ void __launch_bounds__(THREADS, 1)
lstm_fused_kernel(const float* __restrict__ x,
                  const float* __restrict__ Wih0, const float* __restrict__ Whh0,
                  const float* __restrict__ bih0, const float* __restrict__ bhh0,
                  const float* __restrict__ Wih1, const float* __restrict__ Whh1,
                  const float* __restrict__ bih1, const float* __restrict__ bhh1,
                  const float* __restrict__ Wih2, const float* __restrict__ Whh2,
                  const float* __restrict__ bih2, const float* __restrict__ bhh2,
                  const float* __restrict__ Wout, const float* __restrict__ bout,
                  float* __restrict__ out)
{
    const int tid  = threadIdx.x;
    const int bglob = blockIdx.x * BPC;

    // zero IN + C
    for (int i = tid; i < PF; i += THREADS) smf[i] = 0.0f;
    if (tid < Hh) smf[WOF + tid] = Wout[tid];

    // ---- slot mapping: layer (5 warps each), k-half, gate pair ----
    const int layer = tid / 160;
    const int idx2  = tid - layer * 160;
    const int half  = (idx2 >= 80) ? 1 : 0;
    const int lg    = 2 * (idx2 - half * 80);     // even gate 0..158

    // ---- weights into registers (this gate pair, this k-half) ----
    u64 wa[20], wb[20];
    float biasA = 0.0f, biasB = 0.0f;
    {
        const int gA = lg, gB = lg + 1;
        if (layer == 0) {
            if (half == 0) {
                // virtual k 0..23: [x(6) | pad(2) | h0[0..15]]
#pragma unroll
                for (int i = 0; i < 3; i++) {
                    wa[i] = pk(Wih0[gA*6 + 2*i], Wih0[gA*6 + 2*i + 1]);
                    wb[i] = pk(Wih0[gB*6 + 2*i], Wih0[gB*6 + 2*i + 1]);
                }
                wa[3] = 0ULL; wb[3] = 0ULL;
#pragma unroll
                for (int i = 0; i < 8; i++) {
                    wa[4 + i] = pk(Whh0[gA*40 + 2*i], Whh0[gA*40 + 2*i + 1]);
                    wb[4 + i] = pk(Whh0[gB*40 + 2*i], Whh0[gB*40 + 2*i + 1]);
                }
                biasA = bih0[gA] + bhh0[gA];
                biasB = bih0[gB] + bhh0[gB];
            } else {
                // virtual k 24..47 -> h0[16..39]: weights Whh0[.., 16+2i]
#pragma unroll
                for (int i = 0; i < 12; i++) {
                    wa[i] = pk(Whh0[gA*40 + 16 + 2*i], Whh0[gA*40 + 17 + 2*i]);
                    wb[i] = pk(Whh0[gB*40 + 16 + 2*i], Whh0[gB*40 + 17 + 2*i]);
                }
            }
#pragma unroll
            for (int i = 12; i < 20; i++) { wa[i] = 0ULL; wb[i] = 0ULL; }
        } else {
            // L1 half0: Wih1 over h0; half1: Whh1 over h1 (analog for L2)
            const float* wsrc = (layer == 1) ? (half ? Whh1 : Wih1)
                                             : (half ? Whh2 : Wih2);
#pragma unroll
            for (int i = 0; i < 20; i++) {
                wa[i] = pk(wsrc[gA*40 + 2*i], wsrc[gA*40 + 2*i + 1]);
                wb[i] = pk(wsrc[gB*40 + 2*i], wsrc[gB*40 + 2*i + 1]);
            }
            if (half == 0) {
                biasA = (layer == 1) ? (bih1[gA] + bhh1[gA]) : (bih2[gA] + bhh2[gA]);
                biasB = (layer == 1) ? (bih1[gB] + bhh1[gB]) : (bih2[gB] + bhh2[gB]);
            }
        }
    }
    // input base for this slot's k-half
    const int ibase = (layer == 0) ? (half * 24)
                    : (layer == 1) ? (8 + half * 40)
                                   : (48 + half * 40);
    const float* const inb = smf + INF + ibase;
    float* const pout = smf + PF + half * PHALF + layer * (BPC * GSTR) + lg;

    // ---- update-slot precompute: slots tid, tid+480 (840 total) ----
    int uoffP[2], uoffC[2], uoffH[2], ulay[2]; bool uact[2];
#pragma unroll
    for (int j = 0; j < 2; j++) {
        int si = tid + 480 * j;
        uact[j] = si < 840;
        int sc = uact[j] ? si : 0;
        int l = sc / 280, r = sc - l * 280, b = r / 20, u = (r - b * 20) * 2;
        ulay[j]  = l;
        uoffP[j] = PF + l * (BPC * GSTR) + b * GSTR + u;
        uoffC[j] = CF + (l * BPC + b) * Hh + u;
        uoffH[j] = INF + b * ISTR + 8 + 40 * l + u;
    }

    // ---- x staging: threads 0..83 own (b,k) ----
    const int xb = tid / Dd, xk = tid - (tid / Dd) * Dd;
    int gbx = bglob + xb; if (gbx > Bx - 1) gbx = Bx - 1;
    const float* const xptr = x + (size_t)gbx * Tt * Dd + xk;
    float xr = 0.0f;
    if (tid < BPC * Dd) {
        smf[INF + xb * ISTR + xk] = xptr[0];   // x(0)
        xr = xptr[Dd];                          // x(1)
    }

    // ---- projection mapping: warps 0,1 (64 lanes), 4 lanes per batch ----
    const int pb  = tid >> 2;
    const int sub = tid & 3;
    const int pbc = (pb < BPC) ? pb : 0;
    int gbp = bglob + pb; if (gbp > Bx - 1) gbp = Bx - 1;
    const float boutv = bout[0];

    __syncthreads();

    for (int s = 0; s < Tt + 3; s++) {
        // ============== accum phase (all layers/halves concurrent) ========
        if (layer == 0) accum2g<12>(wa, wb, inb, pout, biasA, biasB);
        else            accum2g<20>(wa, wb, inb, pout, biasA, biasB);

        // projection of t=s-3 on warps 0,1 (h2(s-3) stable during accum)
        if (tid < 64 && s >= 3) {
            float ssum = 0.0f;
#pragma unroll
            for (int j = 0; j < 10; j++) {
                int u = sub * 10 + j;
                ssum = fmaf(smf[WOF + u], smf[INF + pbc * ISTR + 88 + u], ssum);
            }
            ssum += __shfl_down_sync(0xffffffffu, ssum, 2, 4);
            ssum += __shfl_down_sync(0xffffffffu, ssum, 1, 4);
            if (sub == 0 && pb < BPC)
                out[(size_t)gbp * Tt + (s - 3)] = ssum + boutv;
        }
        __syncthreads();

        // ============== update phase (840 slots over 480 threads) =========
#pragma unroll
        for (int j = 0; j < 2; j++) {
            int ta = s - ulay[j];
            if (uact[j] && ta >= 0 && ta < Tt) {
                const float* p0 = smf + uoffP[j];
                const float* p1 = p0 + PHALF;
                float* cp = smf + uoffC[j];
                float* hp = smf + uoffH[j];
                float2 A, B;
                A = *(const float2*)(p0);        B = *(const float2*)(p1);
                float i0 = sigf(A.x + B.x),  i1 = sigf(A.y + B.y);
                A = *(const float2*)(p0 + 40);   B = *(const float2*)(p1 + 40);
                float f0 = sigf(A.x + B.x),  f1 = sigf(A.y + B.y);
                A = *(const float2*)(p0 + 80);   B = *(const float2*)(p1 + 80);
                float g0 = tanhf_(A.x + B.x), g1 = tanhf_(A.y + B.y);
                A = *(const float2*)(p0 + 120);  B = *(const float2*)(p1 + 120);
                float o0 = sigf(A.x + B.x),  o1 = sigf(A.y + B.y);
                float2 c = *(const float2*)cp;
                float c0 = fmaf(f0, c.x, i0 * g0), c1 = fmaf(f1, c.y, i1 * g1);
                *(float2*)cp = make_float2(c0, c1);
                *(float2*)hp = make_float2(o0 * tanhf_(c0), o1 * tanhf_(c1));
            }
        }
        // stage x(s+1), prefetch x(s+2)
        if (tid < BPC * Dd) {
            smf[INF + xb * ISTR + xk] = xr;
            int tn = s + 2; if (tn > Tt - 1) tn = Tt - 1;
            xr = xptr[tn * Dd];
        }
        __syncthreads();
    }
}

extern "C" void kernel_launch(void* const* d_in, const int* in_sizes, int n_in,
                              void* d_out, int out_size)
{
    (void)in_sizes; (void)n_in; (void)out_size;
    cudaFuncSetAttribute(lstm_fused_kernel,
                         cudaFuncAttributeMaxDynamicSharedMemorySize,
                         SMF * (int)sizeof(float));
    lstm_fused_kernel<<<NCTA, THREADS, SMF * sizeof(float)>>>(
        (const float*)d_in[0],
        (const float*)d_in[1],  (const float*)d_in[2],
        (const float*)d_in[3],  (const float*)d_in[4],
        (const float*)d_in[5],  (const float*)d_in[6],
        (const float*)d_in[7],  (const float*)d_in[8],
        (const float*)d_in[9],  (const float*)d_in[10],
        (const float*)d_in[11], (const float*)d_in[12],
        (const float*)d_in[13], (const float*)d_in[14],
        (float*)d_out);
}

// round 11
// speedup vs baseline: 1.6624x; 1.0092x over previous
#include <cuda_runtime.h>

#define Bx 2048
#define Tt 512
#define Dd 6
#define Hh 40
#define Gg 160
#define BPC 14
#define GB 7              // batches per group (A: 0..6, B: 7..13)
#define NCTA 147          // 147*14 = 2058 >= 2048
#define THREADS 480       // slots: 3 layers x 80 gate-pairs x 2 k-halves

#define ISTR 132          // IN stride: [x6|pad2|h0 40|h1 40|h2 40|spare4]
#define GSTR 162          // PART stride per batch
#define PHALF (3*BPC*GSTR)

// smem float offsets
#define INF 0
#define CF  (BPC*ISTR)               // C[3][BPC][40]
#define PF  (CF + 3*BPC*Hh)          // PART[2][3][BPC][GSTR]
#define WOF (PF + 2*PHALF)           // Wout[40]
#define SMF (WOF + Hh + 8)

typedef unsigned long long u64;
#define LOG2E 1.4426950408889634f

__device__ __forceinline__ u64 pk(float a, float b) {
    u64 r; asm("mov.b64 %0, {%1, %2};" : "=l"(r) : "f"(a), "f"(b)); return r;
}
__device__ __forceinline__ u64 ffma2(u64 a, u64 b, u64 c) {
    u64 d; asm("fma.rn.f32x2 %0, %1, %2, %3;" : "=l"(d) : "l"(a), "l"(b), "l"(c)); return d;
}
__device__ __forceinline__ u64 add2(u64 a, u64 b) {
    u64 d; asm("add.rn.f32x2 %0, %1, %2;" : "=l"(d) : "l"(a), "l"(b)); return d;
}
__device__ __forceinline__ float ex2f(float x) {
    float y; asm("ex2.approx.f32 %0, %1;" : "=f"(y) : "f"(x)); return y;
}
__device__ __forceinline__ float rcpf(float x) {
    float y; asm("rcp.approx.f32 %0, %1;" : "=f"(y) : "f"(x)); return y;
}
__device__ __forceinline__ float sigf(float x)  { return rcpf(1.0f + ex2f(-LOG2E * x)); }
__device__ __forceinline__ float tanhf_(float x){ return fmaf(2.0f, rcpf(1.0f + ex2f(-2.0f*LOG2E*x)), -1.0f); }

__device__ __forceinline__ void sts64v(float* p, float a, float b) {
    asm volatile("st.shared.v2.f32 [%0], {%1, %2};"
                 :: "l"(__cvta_generic_to_shared(p)), "f"(a), "f"(b) : "memory");
}

// Accumulate 2 gates (A,B) over NU u64 k-pairs (one k-half) for GB batches.
template<int NU>
__device__ __forceinline__ void accum2g(const u64* __restrict__ wa,
                                        const u64* __restrict__ wb,
                                        const float* __restrict__ inb,
                                        float* __restrict__ pout,
                                        float biasA, float biasB)
{
#pragma unroll 2
    for (int b = 0; b < GB; b++) {
        const ulonglong2* hp = (const ulonglong2*)(inb + b * ISTR);
        u64 a0 = 0, a1 = 0, c0 = 0, c1 = 0;
#pragma unroll
        for (int q = 0; q < NU / 2; q++) {
            ulonglong2 v = hp[q];
            a0 = ffma2(wa[2*q],     v.x, a0);
            c0 = ffma2(wb[2*q],     v.x, c0);
            a1 = ffma2(wa[2*q + 1], v.y, a1);
            c1 = ffma2(wb[2*q + 1], v.y, c1);
        }
        a0 = add2(a0, a1); c0 = add2(c0, c1);
        float ua, va, ub, vb;
        asm("mov.b64 {%0, %1}, %2;" : "=f"(ua), "=f"(va) : "l"(a0));
        asm("mov.b64 {%0, %1}, %2;" : "=f"(ub), "=f"(vb) : "l"(c0));
        sts64v(pout + b * GSTR, ua + va + biasA, ub + vb + biasB);
    }
}

// Sum partial halves, activations, write c and h for one unit-pair.
__device__ __forceinline__ void do_update(const float* p0, float* cp, float* hp)
{
    const float* p1 = p0 + PHALF;
    float2 A, B;
    A = *(const float2*)(p0);        B = *(const float2*)(p1);
    float i0 = sigf(A.x + B.x),  i1 = sigf(A.y + B.y);
    A = *(const float2*)(p0 + 40);   B = *(const float2*)(p1 + 40);
    float f0 = sigf(A.x + B.x),  f1 = sigf(A.y + B.y);
    A = *(const float2*)(p0 + 80);   B = *(const float2*)(p1 + 80);
    float g0 = tanhf_(A.x + B.x), g1 = tanhf_(A.y + B.y);
    A = *(const float2*)(p0 + 120);  B = *(const float2*)(p1 + 120);
    float o0 = sigf(A.x + B.x),  o1 = sigf(A.y + B.y);
    float2 c = *(const float2*)cp;
    float c0 = fmaf(f0, c.x, i0 * g0), c1 = fmaf(f1, c.y, i1 * g1);
    *(float2*)cp = make_float2(c0, c1);
    *(float2*)hp = make_float2(o0 * tanhf_(c0), o1 * tanhf_(c1));
}

extern __shared__ float smf[];

__global__ void __launch_bounds__(THREADS, 1)
lstm_fused_kernel(const float* __restrict__ x,
                  const float* __restrict__ Wih0, const float* __restrict__ Whh0,
                  const float* __restrict__ bih0, const float* __restrict__ bhh0,
                  const float* __restrict__ Wih1, const float* __restrict__ Whh1,
                  const float* __restrict__ bih1, const float* __restrict__ bhh1,
                  const float* __restrict__ Wih2, const float* __restrict__ Whh2,
                  const float* __restrict__ bih2, const float* __restrict__ bhh2,
                  const float* __restrict__ Wout, const float* __restrict__ bout,
                  float* __restrict__ out)
{
    const int tid  = threadIdx.x;
    const int w    = tid >> 5;
    const int lane = tid & 31;
    const int bglob = blockIdx.x * BPC;

    // zero IN + C + PART; load Wout
    for (int i = tid; i < PF; i += THREADS) smf[i] = 0.0f;
    if (tid < Hh) smf[WOF + tid] = Wout[tid];

    // ---- slot mapping: layer (5 warps each), k-half, gate pair ----
    const int layer = tid / 160;
    const int idx2  = tid - layer * 160;
    const int half  = (idx2 >= 80) ? 1 : 0;
    const int lg    = 2 * (idx2 - half * 80);     // even gate 0..158

    // ---- weights into registers (this gate pair, this k-half) ----
    u64 wa[20], wb[20];
    float biasA = 0.0f, biasB = 0.0f;
    {
        const int gA = lg, gB = lg + 1;
        if (layer == 0) {
            if (half == 0) {
                // virtual k 0..23: [x(6) | pad(2) | h0[0..15]]
#pragma unroll
                for (int i = 0; i < 3; i++) {
                    wa[i] = pk(Wih0[gA*6 + 2*i], Wih0[gA*6 + 2*i + 1]);
                    wb[i] = pk(Wih0[gB*6 + 2*i], Wih0[gB*6 + 2*i + 1]);
                }
                wa[3] = 0ULL; wb[3] = 0ULL;
#pragma unroll
                for (int i = 0; i < 8; i++) {
                    wa[4 + i] = pk(Whh0[gA*40 + 2*i], Whh0[gA*40 + 2*i + 1]);
                    wb[4 + i] = pk(Whh0[gB*40 + 2*i], Whh0[gB*40 + 2*i + 1]);
                }
                biasA = bih0[gA] + bhh0[gA];
                biasB = bih0[gB] + bhh0[gB];
            } else {
                // virtual k 24..47 -> h0[16..39]
#pragma unroll
                for (int i = 0; i < 12; i++) {
                    wa[i] = pk(Whh0[gA*40 + 16 + 2*i], Whh0[gA*40 + 17 + 2*i]);
                    wb[i] = pk(Whh0[gB*40 + 16 + 2*i], Whh0[gB*40 + 17 + 2*i]);
                }
            }
#pragma unroll
            for (int i = 12; i < 20; i++) { wa[i] = 0ULL; wb[i] = 0ULL; }
        } else {
            const float* wsrc = (layer == 1) ? (half ? Whh1 : Wih1)
                                             : (half ? Whh2 : Wih2);
#pragma unroll
            for (int i = 0; i < 20; i++) {
                wa[i] = pk(wsrc[gA*40 + 2*i], wsrc[gA*40 + 2*i + 1]);
                wb[i] = pk(wsrc[gB*40 + 2*i], wsrc[gB*40 + 2*i + 1]);
            }
            if (half == 0) {
                biasA = (layer == 1) ? (bih1[gA] + bhh1[gA]) : (bih2[gA] + bhh2[gA]);
                biasB = (layer == 1) ? (bih1[gB] + bhh1[gB]) : (bih2[gB] + bhh2[gB]);
            }
        }
    }
    const int ibase = (layer == 0) ? (half * 24)
                    : (layer == 1) ? (8 + half * 40)
                                   : (48 + half * 40);
    const float* const inbA = smf + INF + ibase;             // group A batches 0..6
    const float* const inbB = inbA + GB * ISTR;              // group B batches 7..13
    float* const poutA = smf + PF + half * PHALF + layer * (BPC * GSTR) + lg;
    float* const poutB = poutA + GB * GSTR;

    // ---- update slot (1 per thread, 420 total per group) ----
    const bool uact = tid < 420;
    const int  sc   = uact ? tid : 0;
    const int  ul   = sc / 140;
    const int  ur   = sc - ul * 140;
    const int  ub   = ur / 20;
    const int  uu   = (ur - ub * 20) * 2;
    const int uoffP = PF + ul * (BPC * GSTR) + ub * GSTR + uu;
    const int uoffC = CF + (ul * BPC + ub) * Hh + uu;
    const int uoffH = INF + ub * ISTR + 8 + 40 * ul + uu;

    // ---- x staging ----
    // A: tid 0..41 -> batch tid/6 (0..6); B: tid 42..83 -> batch 7+(tid-42)/6
    float xr = 0.0f;
    const float* xptr = 0;
    int xsm = 0;
    if (tid < 42) {
        int xb = tid / 6, xk = tid - xb * 6;
        int gb = bglob + xb; if (gb > Bx - 1) gb = Bx - 1;
        xptr = x + (size_t)gb * Tt * Dd + xk;
        xsm  = INF + xb * ISTR + xk;
    } else if (tid < 84) {
        int t2 = tid - 42;
        int xb = t2 / 6, xk = t2 - xb * 6;
        int gb = bglob + GB + xb; if (gb > Bx - 1) gb = Bx - 1;
        xptr = x + (size_t)gb * Tt * Dd + xk;
        xsm  = INF + (GB + xb) * ISTR + xk;
    }

    // ---- projection mapping (warp 0): 4 lanes per batch, 7 batches/group ----
    const int pb  = lane >> 2;                 // 0..7
    const int sub = lane & 3;
    const int pbc = (pb < GB) ? pb : (GB - 1);
    const float boutv = bout[0];

    __syncthreads();

    // initial x staging: x_A(0) into smem; prefetch x_A(1) / x_B(0)
    if (tid < 42) { smf[xsm] = xptr[0]; xr = xptr[Dd]; }       // xr = x_A(1)
    else if (tid < 84) { xr = xptr[0]; }                        // xr = x_B(0)
    __syncthreads();

    for (int s = 0; s < Tt + 3; s++) {
        // ================= Phase 1: update(B,s-1) | accum(A,s) =============
        {
            int tu = s - 1 - ul;
            if (uact && tu >= 0 && tu < Tt)
                do_update(smf + uoffP + GB * GSTR,
                          smf + uoffC + GB * Hh,
                          smf + uoffH + GB * ISTR);
        }
        {
            int ta = s - layer;
            if (ta >= 0 && ta < Tt) {
                if (layer == 0) accum2g<12>(wa, wb, inbA, poutA, biasA, biasB);
                else            accum2g<20>(wa, wb, inbA, poutA, biasA, biasB);
            }
        }
        if (w == 0 && s >= 3) {        // proj(A, t=s-3)
            float ssum = 0.0f;
#pragma unroll
            for (int j = 0; j < 10; j++) {
                int u = sub * 10 + j;
                ssum = fmaf(smf[WOF + u], smf[INF + pbc * ISTR + 88 + u], ssum);
            }
            ssum += __shfl_down_sync(0xffffffffu, ssum, 2, 4);
            ssum += __shfl_down_sync(0xffffffffu, ssum, 1, 4);
            int gb = bglob + pb;
            if (sub == 0 && pb < GB && gb < Bx)
                out[(size_t)gb * Tt + (s - 3)] = ssum + boutv;
        }
        if (tid >= 42 && tid < 84) {   // stage x_B(s); prefetch x_B(s+1)
            smf[xsm] = xr;
            int tn = s + 1; if (tn > Tt - 1) tn = Tt - 1;
            xr = xptr[tn * Dd];
        }
        __syncthreads();

        // ================= Phase 2: update(A,s) | accum(B,s) ===============
        {
            int tu = s - ul;
            if (uact && tu >= 0 && tu < Tt)
                do_update(smf + uoffP, smf + uoffC, smf + uoffH);
        }
        {
            int ta = s - layer;
            if (ta >= 0 && ta < Tt) {
                if (layer == 0) accum2g<12>(wa, wb, inbB, poutB, biasA, biasB);
                else            accum2g<20>(wa, wb, inbB, poutB, biasA, biasB);
            }
        }
        if (w == 0 && s >= 3) {        // proj(B, t=s-3)
            float ssum = 0.0f;
#pragma unroll
            for (int j = 0; j < 10; j++) {
                int u = sub * 10 + j;
                ssum = fmaf(smf[WOF + u], smf[INF + (GB + pbc) * ISTR + 88 + u], ssum);
            }
            ssum += __shfl_down_sync(0xffffffffu, ssum, 2, 4);
            ssum += __shfl_down_sync(0xffffffffu, ssum, 1, 4);
            int gb = bglob + GB + pb;
            if (sub == 0 && pb < GB && gb < Bx)
                out[(size_t)gb * Tt + (s - 3)] = ssum + boutv;
        }
        if (tid < 42) {                // stage x_A(s+1); prefetch x_A(s+2)
            smf[xsm] = xr;
            int tn = s + 2; if (tn > Tt - 1) tn = Tt - 1;
            xr = xptr[tn * Dd];
        }
        __syncthreads();
    }
}

extern "C" void kernel_launch(void* const* d_in, const int* in_sizes, int n_in,
                              void* d_out, int out_size)
{
    (void)in_sizes; (void)n_in; (void)out_size;
    cudaFuncSetAttribute(lstm_fused_kernel,
                         cudaFuncAttributeMaxDynamicSharedMemorySize,
                         SMF * (int)sizeof(float));
    lstm_fused_kernel<<<NCTA, THREADS, SMF * sizeof(float)>>>(
        (const float*)d_in[0],
        (const float*)d_in[1],  (const float*)d_in[2],
        (const float*)d_in[3],  (const float*)d_in[4],
        (const float*)d_in[5],  (const float*)d_in[6],
        (const float*)d_in[7],  (const float*)d_in[8],
        (const float*)d_in[9],  (const float*)d_in[10],
        (const float*)d_in[11], (const float*)d_in[12],
        (const float*)d_in[13], (const float*)d_in[14],
        (float*)d_out);
}

// round 12
// speedup vs baseline: 1.6767x; 1.0086x over previous
#include <cuda_runtime.h>

#define Bx 2048
#define Tt 512
#define Dd 6
#define Hh 40
#define Gg 160
#define BPC 14
#define GB 7              // batches per group (A: 0..6, B: 7..13)
#define NCTA 147          // 147*14 = 2058 >= 2048
#define THREADS 480       // slots: 3 layers x 80 gate-pairs x 2 k-halves

#define ISTR 132          // IN stride: [x6|pad2|h0 40|h1 40|h2 40|spare4]
#define GSTR 162          // PART stride per batch
#define PHALF (3*BPC*GSTR)

// smem float offsets
#define INF 0
#define CF  (BPC*ISTR)               // C[3][BPC][40]
#define PF  (CF + 3*BPC*Hh)          // PART[2][3][BPC][GSTR]
#define WOF (PF + 2*PHALF)           // Wout[40]
#define SMF (WOF + Hh + 8)

typedef unsigned long long u64;
#define LOG2E 1.4426950408889634f

__device__ __forceinline__ u64 pk(float a, float b) {
    u64 r; asm("mov.b64 %0, {%1, %2};" : "=l"(r) : "f"(a), "f"(b)); return r;
}
__device__ __forceinline__ u64 ffma2(u64 a, u64 b, u64 c) {
    u64 d; asm("fma.rn.f32x2 %0, %1, %2, %3;" : "=l"(d) : "l"(a), "l"(b), "l"(c)); return d;
}
__device__ __forceinline__ u64 add2(u64 a, u64 b) {
    u64 d; asm("add.rn.f32x2 %0, %1, %2;" : "=l"(d) : "l"(a), "l"(b)); return d;
}
__device__ __forceinline__ float ex2f(float x) {
    float y; asm("ex2.approx.f32 %0, %1;" : "=f"(y) : "f"(x)); return y;
}
__device__ __forceinline__ float rcpf(float x) {
    float y; asm("rcp.approx.f32 %0, %1;" : "=f"(y) : "f"(x)); return y;
}
__device__ __forceinline__ float sigf(float x)  { return rcpf(1.0f + ex2f(-LOG2E * x)); }
__device__ __forceinline__ float tanhf_(float x){ return fmaf(2.0f, rcpf(1.0f + ex2f(-2.0f*LOG2E*x)), -1.0f); }

__device__ __forceinline__ void sts64v(float* p, float a, float b) {
    asm volatile("st.shared.v2.f32 [%0], {%1, %2};"
                 :: "l"(__cvta_generic_to_shared(p)), "f"(a), "f"(b) : "memory");
}

// Accumulate 2 gates (A,B) over NU u64 k-pairs (one k-half) for GB batches.
// Batches processed in interleaved PAIRS: 8 independent FFMA2 chains so one
// batch's loads overlap the other's math (hides LDS latency in-warp).
template<int NU>
__device__ __forceinline__ void accum2g(const u64* __restrict__ wa,
                                        const u64* __restrict__ wb,
                                        const float* __restrict__ inb,
                                        float* __restrict__ pout,
                                        float biasA, float biasB)
{
#pragma unroll
    for (int bp = 0; bp < GB / 2; bp++) {
        const ulonglong2* hp0 = (const ulonglong2*)(inb + (2 * bp)     * ISTR);
        const ulonglong2* hp1 = (const ulonglong2*)(inb + (2 * bp + 1) * ISTR);
        u64 a0 = 0, a1 = 0, c0 = 0, c1 = 0;   // batch even: gates A,B
        u64 d0 = 0, d1 = 0, e0 = 0, e1 = 0;   // batch odd : gates A,B
#pragma unroll
        for (int q = 0; q < NU / 2; q++) {
            ulonglong2 v = hp0[q];
            ulonglong2 u = hp1[q];
            a0 = ffma2(wa[2*q],     v.x, a0);
            d0 = ffma2(wa[2*q],     u.x, d0);
            c0 = ffma2(wb[2*q],     v.x, c0);
            e0 = ffma2(wb[2*q],     u.x, e0);
            a1 = ffma2(wa[2*q + 1], v.y, a1);
            d1 = ffma2(wa[2*q + 1], u.y, d1);
            c1 = ffma2(wb[2*q + 1], v.y, c1);
            e1 = ffma2(wb[2*q + 1], u.y, e1);
        }
        a0 = add2(a0, a1); c0 = add2(c0, c1);
        d0 = add2(d0, d1); e0 = add2(e0, e1);
        float ua, va, ub, vb, uc, vc, ud, vd;
        asm("mov.b64 {%0, %1}, %2;" : "=f"(ua), "=f"(va) : "l"(a0));
        asm("mov.b64 {%0, %1}, %2;" : "=f"(ub), "=f"(vb) : "l"(c0));
        asm("mov.b64 {%0, %1}, %2;" : "=f"(uc), "=f"(vc) : "l"(d0));
        asm("mov.b64 {%0, %1}, %2;" : "=f"(ud), "=f"(vd) : "l"(e0));
        sts64v(pout + (2 * bp)     * GSTR, ua + va + biasA, ub + vb + biasB);
        sts64v(pout + (2 * bp + 1) * GSTR, uc + vc + biasA, ud + vd + biasB);
    }
    // tail batch (GB odd)
    {
        const ulonglong2* hp = (const ulonglong2*)(inb + (GB - 1) * ISTR);
        u64 a0 = 0, a1 = 0, c0 = 0, c1 = 0;
#pragma unroll
        for (int q = 0; q < NU / 2; q++) {
            ulonglong2 v = hp[q];
            a0 = ffma2(wa[2*q],     v.x, a0);
            c0 = ffma2(wb[2*q],     v.x, c0);
            a1 = ffma2(wa[2*q + 1], v.y, a1);
            c1 = ffma2(wb[2*q + 1], v.y, c1);
        }
        a0 = add2(a0, a1); c0 = add2(c0, c1);
        float ua, va, ub, vb;
        asm("mov.b64 {%0, %1}, %2;" : "=f"(ua), "=f"(va) : "l"(a0));
        asm("mov.b64 {%0, %1}, %2;" : "=f"(ub), "=f"(vb) : "l"(c0));
        sts64v(pout + (GB - 1) * GSTR, ua + va + biasA, ub + vb + biasB);
    }
}

// Sum partial halves, activations, write c and h for one unit-pair.
__device__ __forceinline__ void do_update(const float* p0, float* cp, float* hp)
{
    const float* p1 = p0 + PHALF;
    float2 A, B;
    A = *(const float2*)(p0);        B = *(const float2*)(p1);
    float i0 = sigf(A.x + B.x),  i1 = sigf(A.y + B.y);
    A = *(const float2*)(p0 + 40);   B = *(const float2*)(p1 + 40);
    float f0 = sigf(A.x + B.x),  f1 = sigf(A.y + B.y);
    A = *(const float2*)(p0 + 80);   B = *(const float2*)(p1 + 80);
    float g0 = tanhf_(A.x + B.x), g1 = tanhf_(A.y + B.y);
    A = *(const float2*)(p0 + 120);  B = *(const float2*)(p1 + 120);
    float o0 = sigf(A.x + B.x),  o1 = sigf(A.y + B.y);
    float2 c = *(const float2*)cp;
    float c0 = fmaf(f0, c.x, i0 * g0), c1 = fmaf(f1, c.y, i1 * g1);
    *(float2*)cp = make_float2(c0, c1);
    *(float2*)hp = make_float2(o0 * tanhf_(c0), o1 * tanhf_(c1));
}

extern __shared__ float smf[];

__global__ void __launch_bounds__(THREADS, 1)
lstm_fused_kernel(const float* __restrict__ x,
                  const float* __restrict__ Wih0, const float* __restrict__ Whh0,
                  const float* __restrict__ bih0, const float* __restrict__ bhh0,
                  const float* __restrict__ Wih1, const float* __restrict__ Whh1,
                  const float* __restrict__ bih1, const float* __restrict__ bhh1,
                  const float* __restrict__ Wih2, const float* __restrict__ Whh2,
                  const float* __restrict__ bih2, const float* __restrict__ bhh2,
                  const float* __restrict__ Wout, const float* __restrict__ bout,
                  float* __restrict__ out)
{
    const int tid  = threadIdx.x;
    const int w    = tid >> 5;
    const int lane = tid & 31;
    const int bglob = blockIdx.x * BPC;

    // zero IN + C + PART; load Wout
    for (int i = tid; i < PF; i += THREADS) smf[i] = 0.0f;
    if (tid < Hh) smf[WOF + tid] = Wout[tid];

    // ---- slot mapping: layer (5 warps each), k-half, gate pair ----
    const int layer = tid / 160;
    const int idx2  = tid - layer * 160;
    const int half  = (idx2 >= 80) ? 1 : 0;
    const int lg    = 2 * (idx2 - half * 80);     // even gate 0..158

    // ---- weights into registers (this gate pair, this k-half) ----
    u64 wa[20], wb[20];
    float biasA = 0.0f, biasB = 0.0f;
    {
        const int gA = lg, gB = lg + 1;
        if (layer == 0) {
            if (half == 0) {
                // virtual k 0..23: [x(6) | pad(2) | h0[0..15]]
#pragma unroll
                for (int i = 0; i < 3; i++) {
                    wa[i] = pk(Wih0[gA*6 + 2*i], Wih0[gA*6 + 2*i + 1]);
                    wb[i] = pk(Wih0[gB*6 + 2*i], Wih0[gB*6 + 2*i + 1]);
                }
                wa[3] = 0ULL; wb[3] = 0ULL;
#pragma unroll
                for (int i = 0; i < 8; i++) {
                    wa[4 + i] = pk(Whh0[gA*40 + 2*i], Whh0[gA*40 + 2*i + 1]);
                    wb[4 + i] = pk(Whh0[gB*40 + 2*i], Whh0[gB*40 + 2*i + 1]);
                }
                biasA = bih0[gA] + bhh0[gA];
                biasB = bih0[gB] + bhh0[gB];
            } else {
                // virtual k 24..47 -> h0[16..39]
#pragma unroll
                for (int i = 0; i < 12; i++) {
                    wa[i] = pk(Whh0[gA*40 + 16 + 2*i], Whh0[gA*40 + 17 + 2*i]);
                    wb[i] = pk(Whh0[gB*40 + 16 + 2*i], Whh0[gB*40 + 17 + 2*i]);
                }
            }
#pragma unroll
            for (int i = 12; i < 20; i++) { wa[i] = 0ULL; wb[i] = 0ULL; }
        } else {
            const float* wsrc = (layer == 1) ? (half ? Whh1 : Wih1)
                                             : (half ? Whh2 : Wih2);
#pragma unroll
            for (int i = 0; i < 20; i++) {
                wa[i] = pk(wsrc[gA*40 + 2*i], wsrc[gA*40 + 2*i + 1]);
                wb[i] = pk(wsrc[gB*40 + 2*i], wsrc[gB*40 + 2*i + 1]);
            }
            if (half == 0) {
                biasA = (layer == 1) ? (bih1[gA] + bhh1[gA]) : (bih2[gA] + bhh2[gA]);
                biasB = (layer == 1) ? (bih1[gB] + bhh1[gB]) : (bih2[gB] + bhh2[gB]);
            }
        }
    }
    const int ibase = (layer == 0) ? (half * 24)
                    : (layer == 1) ? (8 + half * 40)
                                   : (48 + half * 40);
    const float* const inbA = smf + INF + ibase;             // group A batches 0..6
    const float* const inbB = inbA + GB * ISTR;              // group B batches 7..13
    float* const poutA = smf + PF + half * PHALF + layer * (BPC * GSTR) + lg;
    float* const poutB = poutA + GB * GSTR;

    // ---- update slot (1 per thread, 420 total per group) ----
    const bool uact = tid < 420;
    const int  sc   = uact ? tid : 0;
    const int  ul   = sc / 140;
    const int  ur   = sc - ul * 140;
    const int  ub   = ur / 20;
    const int  uu   = (ur - ub * 20) * 2;
    const int uoffP = PF + ul * (BPC * GSTR) + ub * GSTR + uu;
    const int uoffC = CF + (ul * BPC + ub) * Hh + uu;
    const int uoffH = INF + ub * ISTR + 8 + 40 * ul + uu;

    // ---- x staging ----
    float xr = 0.0f;
    const float* xptr = 0;
    int xsm = 0;
    if (tid < 42) {
        int xb = tid / 6, xk = tid - xb * 6;
        int gb = bglob + xb; if (gb > Bx - 1) gb = Bx - 1;
        xptr = x + (size_t)gb * Tt * Dd + xk;
        xsm  = INF + xb * ISTR + xk;
    } else if (tid < 84) {
        int t2 = tid - 42;
        int xb = t2 / 6, xk = t2 - xb * 6;
        int gb = bglob + GB + xb; if (gb > Bx - 1) gb = Bx - 1;
        xptr = x + (size_t)gb * Tt * Dd + xk;
        xsm  = INF + (GB + xb) * ISTR + xk;
    }

    // ---- projection mapping (warp 0): 4 lanes per batch, 7 batches/group ----
    const int pb  = lane >> 2;                 // 0..7
    const int sub = lane & 3;
    const int pbc = (pb < GB) ? pb : (GB - 1);
    const float boutv = bout[0];

    __syncthreads();

    // initial x staging: x_A(0) into smem; prefetch x_A(1) / x_B(0)
    if (tid < 42) { smf[xsm] = xptr[0]; xr = xptr[Dd]; }       // xr = x_A(1)
    else if (tid < 84) { xr = xptr[0]; }                        // xr = x_B(0)
    __syncthreads();

    for (int s = 0; s < Tt + 3; s++) {
        // ================= Phase 1: update(B,s-1) | accum(A,s) =============
        {
            int tu = s - 1 - ul;
            if (uact && tu >= 0 && tu < Tt)
                do_update(smf + uoffP + GB * GSTR,
                          smf + uoffC + GB * Hh,
                          smf + uoffH + GB * ISTR);
        }
        {
            int ta = s - layer;
            if (ta >= 0 && ta < Tt) {
                if (layer == 0) accum2g<12>(wa, wb, inbA, poutA, biasA, biasB);
                else            accum2g<20>(wa, wb, inbA, poutA, biasA, biasB);
            }
        }
        if (w == 0 && s >= 3) {        // proj(A, t=s-3)
            float ssum = 0.0f;
#pragma unroll
            for (int j = 0; j < 10; j++) {
                int u = sub * 10 + j;
                ssum = fmaf(smf[WOF + u], smf[INF + pbc * ISTR + 88 + u], ssum);
            }
            ssum += __shfl_down_sync(0xffffffffu, ssum, 2, 4);
            ssum += __shfl_down_sync(0xffffffffu, ssum, 1, 4);
            int gb = bglob + pb;
            if (sub == 0 && pb < GB && gb < Bx)
                out[(size_t)gb * Tt + (s - 3)] = ssum + boutv;
        }
        if (tid >= 42 && tid < 84) {   // stage x_B(s); prefetch x_B(s+1)
            smf[xsm] = xr;
            int tn = s + 1; if (tn > Tt - 1) tn = Tt - 1;
            xr = xptr[tn * Dd];
        }
        __syncthreads();

        // ================= Phase 2: update(A,s) | accum(B,s) ===============
        {
            int tu = s - ul;
            if (uact && tu >= 0 && tu < Tt)
                do_update(smf + uoffP, smf + uoffC, smf + uoffH);
        }
        {
            int ta = s - layer;
            if (ta >= 0 && ta < Tt) {
                if (layer == 0) accum2g<12>(wa, wb, inbB, poutB, biasA, biasB);
                else            accum2g<20>(wa, wb, inbB, poutB, biasA, biasB);
            }
        }
        if (w == 0 && s >= 3) {        // proj(B, t=s-3)
            float ssum = 0.0f;
#pragma unroll
            for (int j = 0; j < 10; j++) {
                int u = sub * 10 + j;
                ssum = fmaf(smf[WOF + u], smf[INF + (GB + pbc) * ISTR + 88 + u], ssum);
            }
            ssum += __shfl_down_sync(0xffffffffu, ssum, 2, 4);
            ssum += __shfl_down_sync(0xffffffffu, ssum, 1, 4);
            int gb = bglob + GB + pb;
            if (sub == 0 && pb < GB && gb < Bx)
                out[(size_t)gb * Tt + (s - 3)] = ssum + boutv;
        }
        if (tid < 42) {                // stage x_A(s+1); prefetch x_A(s+2)
            smf[xsm] = xr;
            int tn = s + 2; if (tn > Tt - 1) tn = Tt - 1;
            xr = xptr[tn * Dd];
        }
        __syncthreads();
    }
}

extern "C" void kernel_launch(void* const* d_in, const int* in_sizes, int n_in,
                              void* d_out, int out_size)
{
    (void)in_sizes; (void)n_in; (void)out_size;
    cudaFuncSetAttribute(lstm_fused_kernel,
                         cudaFuncAttributeMaxDynamicSharedMemorySize,
                         SMF * (int)sizeof(float));
    lstm_fused_kernel<<<NCTA, THREADS, SMF * sizeof(float)>>>(
        (const float*)d_in[0],
        (const float*)d_in[1],  (const float*)d_in[2],
        (const float*)d_in[3],  (const float*)d_in[4],
        (const float*)d_in[5],  (const float*)d_in[6],
        (const float*)d_in[7],  (const float*)d_in[8],
        (const float*)d_in[9],  (const float*)d_in[10],
        (const float*)d_in[11], (const float*)d_in[12],
        (const float*)d_in[13], (const float*)d_in[14],
        (float*)d_out);
}